// round 12
// baseline (speedup 1.0000x reference)
#include <cuda_runtime.h>
#include <cuda_bf16.h>
#include <cstdint>
#include <math.h>

#define NLV  4
#define CPL  1024
#define NC   4096
#define IND  512
#define HID  1024
#define OUTD 512
#define MLPD 128
#define G3   3072
#define MEMK 513

#define KP_M   576   // 513 padded

// ---------------- scratch ----------------
__device__ float g_xa2[NLV * 256];
__device__ float g_xap[2 * NLV * 4 * 128];
__device__ float g_zab[NC * 256];
__device__ float g_out[NC * MEMK];
__device__ float g_gi[(size_t)NC * G3];
__device__ float g_gh[(size_t)NC * G3];
__device__ float g_newh[NC * HID];
__device__ float g_lm[NLV * HID];
__device__ float g_cs[NLV * 8 * HID];
__device__ float g_pz[3 * HID];
__device__ float g_pp[3 * 16 * HID];
__device__ float g_pp2[3 * 16 * HID];
__device__ float g_pred[3 * HID];
__device__ float g_delta[NLV * HID];
__device__ float g_mdelta[NLV * HID];
__device__ float g_gop[HID];
__device__ float g_b2d[NLV * OUTD];
__device__ float g_cp[16 * OUTD];

// [hi|lo] bf16 buffers (row length = 2K)
__device__ __align__(16) __nv_bfloat16 g_A2h[(size_t)NC * 2048];
__device__ __align__(16) __nv_bfloat16 g_A2m[(size_t)NC * 2 * KP_M];
__device__ __align__(16) __nv_bfloat16 g_zab2[(size_t)NC * 512];
__device__ __align__(16) __nv_bfloat16 g_W2hh[(size_t)NLV * G3 * 2048];
__device__ __align__(16) __nv_bfloat16 g_W2ih[(size_t)NLV * G3 * 2 * KP_M];
__device__ __align__(16) __nv_bfloat16 g_W1b2[(size_t)NLV * 256 * 2048];
__device__ __align__(16) __nv_bfloat16 g_W2b2[(size_t)NLV * OUTD * 512];

// ================= mma.sync GEMM (3-phase hi/lo, BK=64, 3-stage) =================
#define BN 128
#define BK 64
#define PROW 72

__device__ __forceinline__ void cp16(uint32_t dst, const void* src)
{
    asm volatile("cp.async.cg.shared.global [%0], [%1], 16;" :: "r"(dst), "l"(src));
}
__device__ __forceinline__ void cp_commit() { asm volatile("cp.async.commit_group;"); }
template<int N> __device__ __forceinline__ void cp_wait()
{
    asm volatile("cp.async.wait_group %0;" :: "n"(N));
}
__device__ __forceinline__ void ldsm4(uint32_t& r0, uint32_t& r1, uint32_t& r2, uint32_t& r3,
                                      uint32_t addr)
{
    asm volatile("ldmatrix.sync.aligned.m8n8.x4.shared.b16 {%0,%1,%2,%3}, [%4];"
                 : "=r"(r0), "=r"(r1), "=r"(r2), "=r"(r3) : "r"(addr));
}
__device__ __forceinline__ void mma16816(float* d, const uint32_t* a, const uint32_t* b)
{
    asm volatile("mma.sync.aligned.m16n8k16.row.col.f32.bf16.bf16.f32 "
                 "{%0,%1,%2,%3}, {%4,%5,%6,%7}, {%8,%9}, {%0,%1,%2,%3};"
                 : "+f"(d[0]), "+f"(d[1]), "+f"(d[2]), "+f"(d[3])
                 : "r"(a[0]), "r"(a[1]), "r"(a[2]), "r"(a[3]), "r"(b[0]), "r"(b[1]));
}

// A: [M, 2K] bf16 [hi|lo]; B: [N, 2K] bf16 [hi|lo].
// C = Ahi@Bhi^T + Ahi@Blo^T + Alo@Bhi^T (+bias, opt relu)
template<int BMT>
__global__ void __launch_bounds__(256, BMT == 256 ? 1 : 2)
tgemm(const __nv_bfloat16* __restrict__ A, long sA,
      const __nv_bfloat16* __restrict__ B, long sB,
      float* __restrict__ C, int ldc, long sC,
      int K, const float* __restrict__ bias, int sBias, int act)
{
    constexpr int WM = BMT / 2;
    constexpr int STGB = (BMT + BN) * PROW * 2;
    constexpr int BOFFB = BMT * PROW * 2;
    extern __shared__ __align__(16) char smem[];
    const int tid = threadIdx.x, wid = tid >> 5, lane = tid & 31;
    const int m0 = blockIdx.y * BMT, n0 = blockIdx.x * BN, lvl = blockIdx.z;
    const int lda = 2 * K;
    A += (long)lvl * sA + (long)m0 * lda;
    B += (long)lvl * sB + (long)n0 * lda;
    C += (long)lvl * sC;
    const float* bp = bias ? bias + (long)lvl * sBias + n0 : nullptr;

    const int wm = (wid >> 2) * WM, wn = (wid & 3) * 32;
    const uint32_t sb = (uint32_t)__cvta_generic_to_shared(smem);

    float acc[WM / 16][4][4] = {};
    const int ntp = K / BK, nt = 3 * ntp;
    const int rrow = tid >> 3, rch = tid & 7;

    auto load_tile = [&](int g, int s) {
        int p = (g >= 2 * ntp) ? 2 : (g >= ntp ? 1 : 0);
        int j = g - p * ntp;
        int ao = ((p == 2) ? K : 0) + j * BK;
        int bo = ((p == 1) ? K : 0) + j * BK;
        const __nv_bfloat16* Ag = A + ao;
        const __nv_bfloat16* Bg = B + bo;
        uint32_t base = sb + (uint32_t)s * STGB;
#pragma unroll
        for (int it = 0; it < BMT / 32; it++) {
            int r = rrow + it * 32;
            uint32_t o = (uint32_t)(r * PROW + rch * 8) * 2;
            cp16(base + o, Ag + (long)r * lda + rch * 8);
        }
#pragma unroll
        for (int it = 0; it < 4; it++) {
            int r = rrow + it * 32;
            uint32_t o = (uint32_t)(r * PROW + rch * 8) * 2;
            cp16(base + BOFFB + o, Bg + (long)r * lda + rch * 8);
        }
    };

    load_tile(0, 0); cp_commit();
    load_tile(1, 1); cp_commit();

    int st = 0;
    for (int kt = 0; kt < nt; kt++) {
        cp_wait<1>();
        __syncthreads();
        if (kt + 2 < nt) {
            int s2 = st + 2; if (s2 >= 3) s2 -= 3;
            load_tile(kt + 2, s2); cp_commit();
        }
        uint32_t as = sb + (uint32_t)st * STGB;
        uint32_t bs = as + BOFFB;
#pragma unroll
        for (int ks = 0; ks < 4; ks++) {
            int k0 = ks * 16;
            uint32_t b[4][2];
#pragma unroll
            for (int nb2 = 0; nb2 < 2; nb2++) {
                int n  = wn + nb2 * 16 + (lane & 7) + ((lane & 16) ? 8 : 0);
                int kk = k0 + ((lane & 8) ? 8 : 0);
                uint32_t r0, r1, r2, r3;
                ldsm4(r0, r1, r2, r3, bs + (uint32_t)(n * PROW + kk) * 2);
                b[nb2 * 2][0] = r0; b[nb2 * 2][1] = r1;
                b[nb2 * 2 + 1][0] = r2; b[nb2 * 2 + 1][1] = r3;
            }
#pragma unroll
            for (int mi = 0; mi < WM / 16; mi++) {
                int r  = wm + mi * 16 + (lane & 7) + ((lane & 8) ? 8 : 0);
                int kk = k0 + ((lane & 16) ? 8 : 0);
                uint32_t a[4];
                ldsm4(a[0], a[1], a[2], a[3], as + (uint32_t)(r * PROW + kk) * 2);
#pragma unroll
                for (int ni = 0; ni < 4; ni++)
                    mma16816(acc[mi][ni], a, b[ni]);
            }
        }
        if (++st == 3) st = 0;
    }

    const int tr = lane >> 2, tc = (lane & 3) * 2;
#pragma unroll
    for (int mi = 0; mi < WM / 16; mi++) {
        int r = m0 + wm + mi * 16 + tr;
#pragma unroll
        for (int ni = 0; ni < 4; ni++) {
            int c  = wn + ni * 8 + tc;
            float b0 = bp ? bp[c] : 0.f, b1 = bp ? bp[c + 1] : 0.f;
            float v0 = acc[mi][ni][0] + b0, v1 = acc[mi][ni][1] + b1;
            float v2 = acc[mi][ni][2] + b0, v3 = acc[mi][ni][3] + b1;
            if (act) { v0 = fmaxf(v0, 0.f); v1 = fmaxf(v1, 0.f);
                       v2 = fmaxf(v2, 0.f); v3 = fmaxf(v3, 0.f); }
            C[(long)r * ldc + n0 + c]           = v0;
            C[(long)r * ldc + n0 + c + 1]       = v1;
            C[(long)(r + 8) * ldc + n0 + c]     = v2;
            C[(long)(r + 8) * ldc + n0 + c + 1] = v3;
        }
    }
}

// ================= conversions ([hi|lo], 2K rows) =================
__global__ void split2v_k(const float* __restrict__ src, __nv_bfloat16* __restrict__ dst,
                          int K, long total8)
{
    long i = (long)blockIdx.x * 256 + threadIdx.x;
    if (i >= total8) return;
    int kc = K >> 3;
    long r = i / kc; int k = (int)(i - r * kc) * 8;
    const float* s = src + r * (long)K + k;
    float4 v0 = *(const float4*)s;
    float4 v1 = *(const float4*)(s + 4);
    float vv[8] = {v0.x, v0.y, v0.z, v0.w, v1.x, v1.y, v1.z, v1.w};
    union { __nv_bfloat162 h2[4]; uint4 u; } H, L;
#pragma unroll
    for (int j = 0; j < 4; j++) {
        float a = vv[2 * j], b = vv[2 * j + 1];
        __nv_bfloat16 ah = __float2bfloat16(a), bh = __float2bfloat16(b);
        __nv_bfloat16 al = __float2bfloat16(a - __bfloat162float(ah));
        __nv_bfloat16 bl = __float2bfloat16(b - __bfloat162float(bh));
        H.h2[j] = __nv_bfloat162(ah, bh);
        L.h2[j] = __nv_bfloat162(al, bl);
    }
    __nv_bfloat16* d = dst + r * (2L * K) + k;
    *(uint4*)d = H.u;
    *(uint4*)(d + K) = L.u;
}

// scalar split for strided/padded rows (Wih / mem_in)
__global__ void split2_k(const float* __restrict__ src, int lds,
                         __nv_bfloat16* __restrict__ dst, int K, int Kp, long total)
{
    long i = (long)blockIdx.x * 256 + threadIdx.x;
    if (i >= total) return;
    long r = i / Kp; int k = (int)(i - r * Kp);
    float v = (k < K) ? src[r * (long)lds + k] : 0.f;
    __nv_bfloat16 hi = __float2bfloat16(v);
    __nv_bfloat16 lo = __float2bfloat16(v - __bfloat162float(hi));
    __nv_bfloat16* d = dst + r * (2L * Kp);
    d[k] = hi; d[Kp + k] = lo;
}

__global__ void convW1_k(const float* __restrict__ ea, const float* __restrict__ eg)
{
    long i = (long)blockIdx.x * 256 + threadIdx.x;
    if (i >= 4L * 256 * 1024) return;
    int k = (int)(i & 1023); long t = i >> 10; int n = (int)(t & 255); int l = (int)(t >> 8);
    const float* src = ((n < 128) ? ea : eg) + (long)l * (IND + HID) * MLPD;
    float v = src[(long)(IND + k) * MLPD + (n & 127)];
    __nv_bfloat16 hi = __float2bfloat16(v);
    __nv_bfloat16 lo = __float2bfloat16(v - __bfloat162float(hi));
    __nv_bfloat16* d = g_W1b2 + ((long)l * 256 + n) * 2048;
    d[k] = hi; d[1024 + k] = lo;
}

__global__ void convW2_k(const float* __restrict__ W2a, const float* __restrict__ W2g)
{
    long i = (long)blockIdx.x * 256 + threadIdx.x;
    if (i >= 4L * 512 * 256) return;
    int k = (int)(i & 255); long t = i >> 8; int n = (int)(t & 511); int l = (int)(t >> 9);
    float v = (k < 128) ? W2a[(long)l * MLPD * OUTD + (long)k * OUTD + n]
                        : -W2g[(long)l * MLPD * OUTD + (long)(k - 128) * OUTD + n];
    __nv_bfloat16 hi = __float2bfloat16(v);
    __nv_bfloat16 lo = __float2bfloat16(v - __bfloat162float(hi));
    __nv_bfloat16* d = g_W2b2 + ((long)l * 512 + n) * 512;
    d[k] = hi; d[256 + k] = lo;
}

__global__ void b2diff_k(const float* __restrict__ a, const float* __restrict__ g)
{
    int i = blockIdx.x * 256 + threadIdx.x;
    g_b2d[i] = a[i] - g[i];
}

// ================= tail kernels =================
__global__ void xa_part(const float* __restrict__ x,
                        const float* __restrict__ eaW1, const float* __restrict__ egW1)
{
    int ks = blockIdx.x, l = blockIdx.y, which = blockIdx.z, t = threadIdx.x;
    const float* W = (which ? egW1 : eaW1) + (size_t)l * (IND + HID) * MLPD
                     + (size_t)ks * 128 * MLPD;
    const float* xs = x + ks * 128;
    float s = 0.f;
    for (int i = 0; i < 128; i++) s = fmaf(xs[i], W[(size_t)i * MLPD + t], s);
    g_xap[((which * NLV + l) * 4 + ks) * 128 + t] = s;
}
__global__ void xa_red(const float* __restrict__ eab1, const float* __restrict__ egb1)
{
    int l = blockIdx.x, which = blockIdx.y, t = threadIdx.x;
    const float* b = (which ? egb1 : eab1) + l * MLPD;
    float s = b[t];
    for (int ks = 0; ks < 4; ks++) s += g_xap[((which * NLV + l) * 4 + ks) * 128 + t];
    g_xa2[l * 256 + which * 128 + t] = s;
}

__global__ void tension_kernel()
{
    int c = blockIdx.x, t = threadIdx.x;
    const float* row = g_out + (size_t)c * MEMK;
    float s = 0.f;
#pragma unroll
    for (int q = 0; q < 4; q++) { float v = row[t + 128 * q]; s = fmaf(v, v, s); }
    __shared__ float sm[128];
    sm[t] = s; __syncthreads();
    for (int o = 64; o > 0; o >>= 1) { if (t < o) sm[t] += sm[t + o]; __syncthreads(); }
    if (t == 0) g_out[(size_t)c * MEMK + OUTD] = sm[0] * (1.f / OUTD);
}

__global__ void gate_kernel(const float* __restrict__ hid)
{
    int i4 = blockIdx.x * 256 + threadIdx.x;
    int c = i4 >> 8, j4 = (i4 & 255) * 4;
    size_t base = (size_t)c * G3 + j4;
    float4 ir = *(const float4*)(g_gi + base);
    float4 iz = *(const float4*)(g_gi + base + HID);
    float4 in = *(const float4*)(g_gi + base + 2 * HID);
    float4 hr = *(const float4*)(g_gh + base);
    float4 hz = *(const float4*)(g_gh + base + HID);
    float4 hn = *(const float4*)(g_gh + base + 2 * HID);
    float4 hv = *(const float4*)(hid + (size_t)c * HID + j4);
    float4 o;
    {
        float r = 1.f / (1.f + expf(-(ir.x + hr.x)));
        float z = 1.f / (1.f + expf(-(iz.x + hz.x)));
        o.x = (1.f - z) * tanhf(in.x + r * hn.x) + z * hv.x;
        r = 1.f / (1.f + expf(-(ir.y + hr.y)));
        z = 1.f / (1.f + expf(-(iz.y + hz.y)));
        o.y = (1.f - z) * tanhf(in.y + r * hn.y) + z * hv.y;
        r = 1.f / (1.f + expf(-(ir.z + hr.z)));
        z = 1.f / (1.f + expf(-(iz.z + hz.z)));
        o.z = (1.f - z) * tanhf(in.z + r * hn.z) + z * hv.z;
        r = 1.f / (1.f + expf(-(ir.w + hr.w)));
        z = 1.f / (1.f + expf(-(iz.w + hz.w)));
        o.w = (1.f - z) * tanhf(in.w + r * hn.w) + z * hv.w;
    }
    *(float4*)(g_newh + (size_t)c * HID + j4) = o;
}

__global__ void colsum_part()
{
    int jb = blockIdx.x, l = blockIdx.y, cs = blockIdx.z, t = threadIdx.x;
    int j = jb * 128 + t;
    const float* p = g_newh + ((size_t)(l * CPL + cs * 128)) * HID + j;
    float s = 0.f;
    for (int c = 0; c < 128; c++) s += p[(size_t)c * HID];
    g_cs[(l * 8 + cs) * HID + j] = s;
}
__global__ void colsum_red()
{
    int jb = blockIdx.x, l = blockIdx.y, t = threadIdx.x;
    int j = jb * 128 + t;
    float s = 0.f;
    for (int cs = 0; cs < 8; cs++) s += g_cs[(l * 8 + cs) * HID + j];
    g_lm[l * HID + j] = s * (1.f / CPL);
}

template<int SRC>
__global__ void pred_part(const float* __restrict__ W)
{
    int ks = blockIdx.x, l = blockIdx.y, t = threadIdx.x;
    const float* v = (SRC == 0 ? g_lm + (l + 1) * HID : g_pz + l * HID) + ks * 64;
    const float* Wp = W + (size_t)l * HID * HID + (size_t)ks * 64 * HID;
    float acc[4] = {0.f, 0.f, 0.f, 0.f};
    for (int i = 0; i < 64; i++) {
        float a = v[i];
#pragma unroll
        for (int q = 0; q < 4; q++) acc[q] = fmaf(a, Wp[(size_t)i * HID + t + 256 * q], acc[q]);
    }
    float* dst = (SRC == 0 ? g_pp : g_pp2) + (l * 16 + ks) * HID;
#pragma unroll
    for (int q = 0; q < 4; q++) dst[t + 256 * q] = acc[q];
}
template<int SRC>
__global__ void pred_red(const float* __restrict__ b)
{
    int l = blockIdx.x, t = threadIdx.x;
    const float* part = (SRC == 0 ? g_pp : g_pp2) + l * 16 * HID;
#pragma unroll
    for (int q = 0; q < 4; q++) {
        int n = t + 256 * q;
        float s = b[l * HID + n];
        for (int ks = 0; ks < 16; ks++) s += part[ks * HID + n];
        if (SRC == 0) g_pz[l * HID + n] = fmaxf(s, 0.f);
        else          g_pred[l * HID + n] = s;
    }
}

__global__ void finalize_kernel()
{
    int j = threadIdx.x;
    float lm0 = g_lm[j], lm1 = g_lm[HID + j], lm2 = g_lm[2 * HID + j], lm3 = g_lm[3 * HID + j];
    float pe0 = (g_pred[j] - lm0) * 0.05f;
    float pe1 = (g_pred[HID + j] - lm1) * 0.05f;
    float pe2 = (g_pred[2 * HID + j] - lm2) * 0.05f;
    float d0 = pe0, d1 = pe1 - 0.5f * pe0, d2 = pe2 - 0.5f * pe1, d3 = -0.5f * pe2;
    g_delta[j] = d0; g_delta[HID + j] = d1; g_delta[2 * HID + j] = d2; g_delta[3 * HID + j] = d3;
    float m0 = lm0 + d0, m1 = lm1 + d1, m2 = lm2 + d2, m3 = lm3 + d3;
    g_mdelta[j] = m0; g_mdelta[HID + j] = m1; g_mdelta[2 * HID + j] = m2; g_mdelta[3 * HID + j] = m3;
    g_gop[j] = (m0 + m1 + m2 + m3) * 0.25f;
}

__global__ void hh_kernel(float* __restrict__ out, const int* __restrict__ stepp)
{
    int idx = blockIdx.x * blockDim.x + threadIdx.x;
    int c = idx >> 10, j = idx & 1023;
    int l = c >> 10, cl = c & 1023;
    float d = g_delta[l * HID + j];
    float v = 0.7225f * (g_newh[idx] + d) + 0.2775f * g_mdelta[l * HID + j];
    if (*stepp > 5 && cl < (CPL / 4)) v = 0.85f * v + 0.15f * g_gop[j];
    out[513 + idx] = v;
}

__global__ void combined_part(const float* __restrict__ W)
{
    int ks = blockIdx.x, nb = blockIdx.y, t = threadIdx.x;
    int n = nb * 256 + t;
    const float* Wp = W + (size_t)ks * 256 * OUTD;
    const float* lm = g_lm + ks * 256;
    float s = 0.f;
    for (int i = 0; i < 256; i++) s = fmaf(lm[i], Wp[(size_t)i * OUTD + n], s);
    g_cp[ks * OUTD + n] = s;
}
__global__ void combined_red(const float* __restrict__ b, float* __restrict__ out)
{
    int n = blockIdx.x * 256 + threadIdx.x;
    float s = b[n];
    for (int ks = 0; ks < 16; ks++) s += g_cp[ks * OUTD + n];
    out[n] = s;
}

__global__ void avgten_kernel(float* __restrict__ out)
{
    __shared__ float sm[1024];
    int t = threadIdx.x;
    float s = 0.f;
#pragma unroll
    for (int q = 0; q < 4; q++) s += g_out[(size_t)(t + 1024 * q) * MEMK + OUTD];
    sm[t] = s; __syncthreads();
    for (int o = 512; o > 0; o >>= 1) { if (t < o) sm[t] += sm[t + o]; __syncthreads(); }
    if (t == 0) out[OUTD] = sm[0] * (1.f / NC);
}

// ================= host =================
template<class T> static T* sym(const T& s)
{
    void* p = nullptr;
    cudaGetSymbolAddress(&p, s);
    return (T*)p;
}

extern "C" void kernel_launch(void* const* d_in, const int* in_sizes, int n_in,
                              void* d_out, int out_size)
{
    const float* x     = (const float*)d_in[0];
    const float* hid   = (const float*)d_in[1];
    const float* eaW1  = (const float*)d_in[2];
    const float* eab1  = (const float*)d_in[3];
    const float* eaW2  = (const float*)d_in[4];
    const float* eab2  = (const float*)d_in[5];
    const float* egW1  = (const float*)d_in[6];
    const float* egb1  = (const float*)d_in[7];
    const float* egW2  = (const float*)d_in[8];
    const float* egb2  = (const float*)d_in[9];
    const float* Wih   = (const float*)d_in[10];
    const float* Whh   = (const float*)d_in[11];
    const float* bih   = (const float*)d_in[12];
    const float* bhh   = (const float*)d_in[13];
    const float* pW1   = (const float*)d_in[14];
    const float* pb1   = (const float*)d_in[15];
    const float* pW2   = (const float*)d_in[16];
    const float* pb2   = (const float*)d_in[17];
    const float* peiW  = (const float*)d_in[18];
    const float* peib  = (const float*)d_in[19];
    const int*   stepp = (const int*)d_in[20];
    float* out = (float*)d_out;

    const int SM256 = 3 * (256 + BN) * PROW * 2;   // 165888
    const int SM64  = 3 * (64 + BN) * PROW * 2;    // 82944
    cudaFuncSetAttribute(tgemm<256>, cudaFuncAttributeMaxDynamicSharedMemorySize, SM256);
    cudaFuncSetAttribute(tgemm<64>,  cudaFuncAttributeMaxDynamicSharedMemorySize, SM64);

    float* zab  = sym(g_zab[0]);
    float* outb = sym(g_out[0]);
    float* gi   = sym(g_gi[0]);
    float* gh   = sym(g_gh[0]);
    float* xa2  = sym(g_xa2[0]);
    float* b2d  = sym(g_b2d[0]);
    __nv_bfloat16* A2h  = sym(g_A2h[0]);
    __nv_bfloat16* A2m  = sym(g_A2m[0]);
    __nv_bfloat16* zab2 = sym(g_zab2[0]);
    __nv_bfloat16* W2hh = sym(g_W2hh[0]);
    __nv_bfloat16* W2ih = sym(g_W2ih[0]);
    __nv_bfloat16* W1b2 = sym(g_W1b2[0]);
    __nv_bfloat16* W2b2 = sym(g_W2b2[0]);

    auto nb = [](long total) { return (unsigned)((total + 255) / 256); };

    // ---- conversions ----
    xa_part<<<dim3(4, NLV, 2), 128>>>(x, eaW1, egW1);
    xa_red<<<dim3(NLV, 2), 128>>>(eab1, egb1);
    convW1_k<<<nb(4L * 256 * 1024), 256>>>(eaW1, egW1);
    convW2_k<<<nb(4L * 512 * 256), 256>>>(eaW2, egW2);
    b2diff_k<<<8, 256>>>(eab2, egb2);
    split2v_k<<<nb((long)NC * 1024 / 8), 256>>>(hid, A2h, 1024, (long)NC * 1024 / 8);
    split2v_k<<<nb((long)NLV * G3 * 1024 / 8), 256>>>(Whh, W2hh, 1024,
                                                      (long)NLV * G3 * 1024 / 8);
    split2_k<<<nb((long)NLV * G3 * KP_M), 256>>>(Wih, MEMK, W2ih, MEMK, KP_M,
                                                 (long)NLV * G3 * KP_M);

    // ---- MLP1: [za|zg] = relu(h @ [W1a;W1g]^T + xa2) ----
    tgemm<64><<<dim3(256 / BN, CPL / 64, NLV), 256, SM64>>>(
        A2h, (long)CPL * 2048, W1b2, 256L * 2048,
        zab, 256, (long)CPL * 256, 1024, xa2, 256, 1);

    // ---- MLP2: out = [za|zg] @ [W2a;-W2g]^T + (b2a-b2g) ----
    split2v_k<<<nb((long)NC * 256 / 8), 256>>>(zab, zab2, 256, (long)NC * 256 / 8);
    tgemm<64><<<dim3(OUTD / BN, CPL / 64, NLV), 256, SM64>>>(
        zab2, (long)CPL * 512, W2b2, (long)OUTD * 512,
        outb, MEMK, (long)CPL * MEMK, 256, b2d, OUTD, 0);

    // ---- tension + mem_in split ----
    tension_kernel<<<NC, 128>>>();
    split2_k<<<nb((long)NC * KP_M), 256>>>(outb, MEMK, A2m, MEMK, KP_M, (long)NC * KP_M);

    // ---- GRU gi / gh (BM=256 tiles) ----
    tgemm<256><<<dim3(G3 / BN, CPL / 256, NLV), 256, SM256>>>(
        A2m, (long)CPL * 2 * KP_M, W2ih, (long)G3 * 2 * KP_M,
        gi, G3, (long)CPL * G3, KP_M, bih, G3, 0);
    tgemm<256><<<dim3(G3 / BN, CPL / 256, NLV), 256, SM256>>>(
        A2h, (long)CPL * 2048, W2hh, (long)G3 * 2048,
        gh, G3, (long)CPL * G3, 1024, bhh, G3, 0);

    // ---- gates + epilogue chain ----
    gate_kernel<<<(NC * HID / 4) / 256, 256>>>(hid);
    colsum_part<<<dim3(8, NLV, 8), 128>>>();
    colsum_red<<<dim3(8, NLV), 128>>>();
    pred_part<0><<<dim3(16, 3), 256>>>(pW1);
    pred_red<0><<<3, 256>>>(pb1);
    pred_part<1><<<dim3(16, 3), 256>>>(pW2);
    pred_red<1><<<3, 256>>>(pb2);
    finalize_kernel<<<1, 1024>>>();
    hh_kernel<<<(NC * HID) / 256, 256>>>(out, stepp);
    combined_part<<<dim3(16, 2), 256>>>(peiW);
    combined_red<<<2, 256>>>(peib, out);
    avgten_kernel<<<1, 1024>>>(out);
}

// round 13
// speedup vs baseline: 1.0735x; 1.0735x over previous
#include <cuda_runtime.h>
#include <cuda_bf16.h>
#include <cstdint>
#include <math.h>

#define NLV  4
#define CPL  1024
#define NC   4096
#define IND  512
#define HID  1024
#define OUTD 512
#define MLPD 128
#define G3   3072
#define MEMK 513

#define KP_M   576   // 513 padded

// ---------------- scratch ----------------
__device__ float g_xa2[NLV * 256];
__device__ float g_xap[2 * NLV * 4 * 128];
__device__ float g_zab[NC * 256];
__device__ float g_out[NC * MEMK];
__device__ float g_gi[(size_t)NC * G3];
__device__ float g_gh[(size_t)NC * G3];
__device__ float g_newh[NC * HID];
__device__ float g_lm[NLV * HID];
__device__ float g_cs[NLV * 8 * HID];
__device__ float g_pz[3 * HID];
__device__ float g_pp[3 * 16 * HID];
__device__ float g_pp2[3 * 16 * HID];
__device__ float g_pred[3 * HID];
__device__ float g_delta[NLV * HID];
__device__ float g_mdelta[NLV * HID];
__device__ float g_gop[HID];
__device__ float g_b2d[NLV * OUTD];
__device__ float g_cp[16 * OUTD];

// [hi|lo] bf16 buffers (row length = 2K)
__device__ __align__(16) __nv_bfloat16 g_A2h[(size_t)NC * 2048];
__device__ __align__(16) __nv_bfloat16 g_A2m[(size_t)NC * 2 * KP_M];
__device__ __align__(16) __nv_bfloat16 g_zab2[(size_t)NC * 512];
__device__ __align__(16) __nv_bfloat16 g_W2hh[(size_t)NLV * G3 * 2048];
__device__ __align__(16) __nv_bfloat16 g_W2ih[(size_t)NLV * G3 * 2 * KP_M];
__device__ __align__(16) __nv_bfloat16 g_W1b2[(size_t)NLV * 256 * 2048];
__device__ __align__(16) __nv_bfloat16 g_W2b2[(size_t)NLV * OUTD * 512];

// ================= mma.sync GEMM (3-phase hi/lo, BK=64, 3-stage) =================
#define BN 128
#define BK 64
#define PROW 72

__device__ __forceinline__ void cp16(uint32_t dst, const void* src)
{
    asm volatile("cp.async.cg.shared.global [%0], [%1], 16;" :: "r"(dst), "l"(src));
}
__device__ __forceinline__ void cp_commit() { asm volatile("cp.async.commit_group;"); }
template<int N> __device__ __forceinline__ void cp_wait()
{
    asm volatile("cp.async.wait_group %0;" :: "n"(N));
}
__device__ __forceinline__ void ldsm4(uint32_t& r0, uint32_t& r1, uint32_t& r2, uint32_t& r3,
                                      uint32_t addr)
{
    asm volatile("ldmatrix.sync.aligned.m8n8.x4.shared.b16 {%0,%1,%2,%3}, [%4];"
                 : "=r"(r0), "=r"(r1), "=r"(r2), "=r"(r3) : "r"(addr));
}
__device__ __forceinline__ void mma16816(float* d, const uint32_t* a, const uint32_t* b)
{
    asm volatile("mma.sync.aligned.m16n8k16.row.col.f32.bf16.bf16.f32 "
                 "{%0,%1,%2,%3}, {%4,%5,%6,%7}, {%8,%9}, {%0,%1,%2,%3};"
                 : "+f"(d[0]), "+f"(d[1]), "+f"(d[2]), "+f"(d[3])
                 : "r"(a[0]), "r"(a[1]), "r"(a[2]), "r"(a[3]), "r"(b[0]), "r"(b[1]));
}

// A: [M, 2K] bf16 [hi|lo]; B: [N, 2K] bf16 [hi|lo].
// C = Ahi@Bhi^T + Ahi@Blo^T + Alo@Bhi^T (+bias, opt relu)
template<int BMT>
__global__ void __launch_bounds__(256, 2)
tgemm(const __nv_bfloat16* __restrict__ A, long sA,
      const __nv_bfloat16* __restrict__ B, long sB,
      float* __restrict__ C, int ldc, long sC,
      int K, const float* __restrict__ bias, int sBias, int act)
{
    constexpr int WM = BMT / 2;
    constexpr int STGB = (BMT + BN) * PROW * 2;
    constexpr int BOFFB = BMT * PROW * 2;
    extern __shared__ __align__(16) char smem[];
    const int tid = threadIdx.x, wid = tid >> 5, lane = tid & 31;
    const int m0 = blockIdx.y * BMT, n0 = blockIdx.x * BN, lvl = blockIdx.z;
    const int lda = 2 * K;
    A += (long)lvl * sA + (long)m0 * lda;
    B += (long)lvl * sB + (long)n0 * lda;
    C += (long)lvl * sC;
    const float* bp = bias ? bias + (long)lvl * sBias + n0 : nullptr;

    const int wm = (wid >> 2) * WM, wn = (wid & 3) * 32;
    const uint32_t sb = (uint32_t)__cvta_generic_to_shared(smem);

    float acc[WM / 16][4][4] = {};
    const int ntp = K / BK, nt = 3 * ntp;
    const int rrow = tid >> 3, rch = tid & 7;

    auto load_tile = [&](int g, int s) {
        int p = (g >= 2 * ntp) ? 2 : (g >= ntp ? 1 : 0);
        int j = g - p * ntp;
        int ao = ((p == 2) ? K : 0) + j * BK;
        int bo = ((p == 1) ? K : 0) + j * BK;
        const __nv_bfloat16* Ag = A + ao;
        const __nv_bfloat16* Bg = B + bo;
        uint32_t base = sb + (uint32_t)s * STGB;
#pragma unroll
        for (int it = 0; it < BMT / 32; it++) {
            int r = rrow + it * 32;
            uint32_t o = (uint32_t)(r * PROW + rch * 8) * 2;
            cp16(base + o, Ag + (long)r * lda + rch * 8);
        }
#pragma unroll
        for (int it = 0; it < 4; it++) {
            int r = rrow + it * 32;
            uint32_t o = (uint32_t)(r * PROW + rch * 8) * 2;
            cp16(base + BOFFB + o, Bg + (long)r * lda + rch * 8);
        }
    };

    load_tile(0, 0); cp_commit();
    load_tile(1, 1); cp_commit();

    int st = 0;
    for (int kt = 0; kt < nt; kt++) {
        cp_wait<1>();
        __syncthreads();
        if (kt + 2 < nt) {
            int s2 = st + 2; if (s2 >= 3) s2 -= 3;
            load_tile(kt + 2, s2); cp_commit();
        }
        uint32_t as = sb + (uint32_t)st * STGB;
        uint32_t bs = as + BOFFB;
#pragma unroll
        for (int ks = 0; ks < 4; ks++) {
            int k0 = ks * 16;
            uint32_t b[4][2];
#pragma unroll
            for (int nb2 = 0; nb2 < 2; nb2++) {
                int n  = wn + nb2 * 16 + (lane & 7) + ((lane & 16) ? 8 : 0);
                int kk = k0 + ((lane & 8) ? 8 : 0);
                uint32_t r0, r1, r2, r3;
                ldsm4(r0, r1, r2, r3, bs + (uint32_t)(n * PROW + kk) * 2);
                b[nb2 * 2][0] = r0; b[nb2 * 2][1] = r1;
                b[nb2 * 2 + 1][0] = r2; b[nb2 * 2 + 1][1] = r3;
            }
#pragma unroll
            for (int mi = 0; mi < WM / 16; mi++) {
                int r  = wm + mi * 16 + (lane & 7) + ((lane & 8) ? 8 : 0);
                int kk = k0 + ((lane & 16) ? 8 : 0);
                uint32_t a[4];
                ldsm4(a[0], a[1], a[2], a[3], as + (uint32_t)(r * PROW + kk) * 2);
#pragma unroll
                for (int ni = 0; ni < 4; ni++)
                    mma16816(acc[mi][ni], a, b[ni]);
            }
        }
        if (++st == 3) st = 0;
    }

    const int tr = lane >> 2, tc = (lane & 3) * 2;
#pragma unroll
    for (int mi = 0; mi < WM / 16; mi++) {
        int r = m0 + wm + mi * 16 + tr;
#pragma unroll
        for (int ni = 0; ni < 4; ni++) {
            int c  = wn + ni * 8 + tc;
            float b0 = bp ? bp[c] : 0.f, b1 = bp ? bp[c + 1] : 0.f;
            float v0 = acc[mi][ni][0] + b0, v1 = acc[mi][ni][1] + b1;
            float v2 = acc[mi][ni][2] + b0, v3 = acc[mi][ni][3] + b1;
            if (act) { v0 = fmaxf(v0, 0.f); v1 = fmaxf(v1, 0.f);
                       v2 = fmaxf(v2, 0.f); v3 = fmaxf(v3, 0.f); }
            C[(long)r * ldc + n0 + c]           = v0;
            C[(long)r * ldc + n0 + c + 1]       = v1;
            C[(long)(r + 8) * ldc + n0 + c]     = v2;
            C[(long)(r + 8) * ldc + n0 + c + 1] = v3;
        }
    }
}

// ================= conversions ([hi|lo], 2K rows) =================
__global__ void split2v_k(const float* __restrict__ src, __nv_bfloat16* __restrict__ dst,
                          int K, long total8)
{
    long i = (long)blockIdx.x * 256 + threadIdx.x;
    if (i >= total8) return;
    int kc = K >> 3;
    long r = i / kc; int k = (int)(i - r * kc) * 8;
    const float* s = src + r * (long)K + k;
    float4 v0 = *(const float4*)s;
    float4 v1 = *(const float4*)(s + 4);
    float vv[8] = {v0.x, v0.y, v0.z, v0.w, v1.x, v1.y, v1.z, v1.w};
    union { __nv_bfloat162 h2[4]; uint4 u; } H, L;
#pragma unroll
    for (int j = 0; j < 4; j++) {
        float a = vv[2 * j], b = vv[2 * j + 1];
        __nv_bfloat16 ah = __float2bfloat16(a), bh = __float2bfloat16(b);
        __nv_bfloat16 al = __float2bfloat16(a - __bfloat162float(ah));
        __nv_bfloat16 bl = __float2bfloat16(b - __bfloat162float(bh));
        H.h2[j] = __nv_bfloat162(ah, bh);
        L.h2[j] = __nv_bfloat162(al, bl);
    }
    __nv_bfloat16* d = dst + r * (2L * K) + k;
    *(uint4*)d = H.u;
    *(uint4*)(d + K) = L.u;
}

// vectorized split for strided/padded rows (K=513 -> Kp=576): scalar guarded
// loads, uint4 stores.
__global__ void split2pv_k(const float* __restrict__ src, int lds,
                           __nv_bfloat16* __restrict__ dst, int K, int Kp, long total8)
{
    long i = (long)blockIdx.x * 256 + threadIdx.x;
    if (i >= total8) return;
    int ch = Kp >> 3;
    long r = i / ch; int kb = (int)(i - r * ch) * 8;
    const float* s = src + r * (long)lds + kb;
    union { __nv_bfloat162 h2[4]; uint4 u; } H, L;
#pragma unroll
    for (int j = 0; j < 4; j++) {
        int k0 = kb + 2 * j, k1 = kb + 2 * j + 1;
        float a = (k0 < K) ? s[2 * j] : 0.f;
        float b = (k1 < K) ? s[2 * j + 1] : 0.f;
        __nv_bfloat16 ah = __float2bfloat16(a), bh = __float2bfloat16(b);
        H.h2[j] = __nv_bfloat162(ah, bh);
        L.h2[j] = __nv_bfloat162(__float2bfloat16(a - __bfloat162float(ah)),
                                 __float2bfloat16(b - __bfloat162float(bh)));
    }
    __nv_bfloat16* d = dst + r * (2L * Kp) + kb;
    *(uint4*)d = H.u;
    *(uint4*)(d + Kp) = L.u;
}

__global__ void convW1_k(const float* __restrict__ ea, const float* __restrict__ eg)
{
    long i = (long)blockIdx.x * 256 + threadIdx.x;
    if (i >= 4L * 256 * 1024) return;
    int k = (int)(i & 1023); long t = i >> 10; int n = (int)(t & 255); int l = (int)(t >> 8);
    const float* src = ((n < 128) ? ea : eg) + (long)l * (IND + HID) * MLPD;
    float v = src[(long)(IND + k) * MLPD + (n & 127)];
    __nv_bfloat16 hi = __float2bfloat16(v);
    __nv_bfloat16 lo = __float2bfloat16(v - __bfloat162float(hi));
    __nv_bfloat16* d = g_W1b2 + ((long)l * 256 + n) * 2048;
    d[k] = hi; d[1024 + k] = lo;
}

__global__ void convW2_k(const float* __restrict__ W2a, const float* __restrict__ W2g)
{
    long i = (long)blockIdx.x * 256 + threadIdx.x;
    if (i >= 4L * 512 * 256) return;
    int k = (int)(i & 255); long t = i >> 8; int n = (int)(t & 511); int l = (int)(t >> 9);
    float v = (k < 128) ? W2a[(long)l * MLPD * OUTD + (long)k * OUTD + n]
                        : -W2g[(long)l * MLPD * OUTD + (long)(k - 128) * OUTD + n];
    __nv_bfloat16 hi = __float2bfloat16(v);
    __nv_bfloat16 lo = __float2bfloat16(v - __bfloat162float(hi));
    __nv_bfloat16* d = g_W2b2 + ((long)l * 512 + n) * 512;
    d[k] = hi; d[256 + k] = lo;
}

__global__ void b2diff_k(const float* __restrict__ a, const float* __restrict__ g)
{
    int i = blockIdx.x * 256 + threadIdx.x;
    g_b2d[i] = a[i] - g[i];
}

// ================= tail kernels =================
__global__ void xa_part(const float* __restrict__ x,
                        const float* __restrict__ eaW1, const float* __restrict__ egW1)
{
    int ks = blockIdx.x, l = blockIdx.y, which = blockIdx.z, t = threadIdx.x;
    const float* W = (which ? egW1 : eaW1) + (size_t)l * (IND + HID) * MLPD
                     + (size_t)ks * 128 * MLPD;
    const float* xs = x + ks * 128;
    float s = 0.f;
    for (int i = 0; i < 128; i++) s = fmaf(xs[i], W[(size_t)i * MLPD + t], s);
    g_xap[((which * NLV + l) * 4 + ks) * 128 + t] = s;
}
__global__ void xa_red(const float* __restrict__ eab1, const float* __restrict__ egb1)
{
    int l = blockIdx.x, which = blockIdx.y, t = threadIdx.x;
    const float* b = (which ? egb1 : eab1) + l * MLPD;
    float s = b[t];
    for (int ks = 0; ks < 4; ks++) s += g_xap[((which * NLV + l) * 4 + ks) * 128 + t];
    g_xa2[l * 256 + which * 128 + t] = s;
}

__global__ void tension_kernel()
{
    int c = blockIdx.x, t = threadIdx.x;
    const float* row = g_out + (size_t)c * MEMK;
    float s = 0.f;
#pragma unroll
    for (int q = 0; q < 4; q++) { float v = row[t + 128 * q]; s = fmaf(v, v, s); }
    __shared__ float sm[128];
    sm[t] = s; __syncthreads();
    for (int o = 64; o > 0; o >>= 1) { if (t < o) sm[t] += sm[t + o]; __syncthreads(); }
    if (t == 0) g_out[(size_t)c * MEMK + OUTD] = sm[0] * (1.f / OUTD);
}

__global__ void gate_kernel(const float* __restrict__ hid)
{
    int i4 = blockIdx.x * 256 + threadIdx.x;
    int c = i4 >> 8, j4 = (i4 & 255) * 4;
    size_t base = (size_t)c * G3 + j4;
    float4 ir = *(const float4*)(g_gi + base);
    float4 iz = *(const float4*)(g_gi + base + HID);
    float4 in = *(const float4*)(g_gi + base + 2 * HID);
    float4 hr = *(const float4*)(g_gh + base);
    float4 hz = *(const float4*)(g_gh + base + HID);
    float4 hn = *(const float4*)(g_gh + base + 2 * HID);
    float4 hv = *(const float4*)(hid + (size_t)c * HID + j4);
    float4 o;
    {
        float r = 1.f / (1.f + expf(-(ir.x + hr.x)));
        float z = 1.f / (1.f + expf(-(iz.x + hz.x)));
        o.x = (1.f - z) * tanhf(in.x + r * hn.x) + z * hv.x;
        r = 1.f / (1.f + expf(-(ir.y + hr.y)));
        z = 1.f / (1.f + expf(-(iz.y + hz.y)));
        o.y = (1.f - z) * tanhf(in.y + r * hn.y) + z * hv.y;
        r = 1.f / (1.f + expf(-(ir.z + hr.z)));
        z = 1.f / (1.f + expf(-(iz.z + hz.z)));
        o.z = (1.f - z) * tanhf(in.z + r * hn.z) + z * hv.z;
        r = 1.f / (1.f + expf(-(ir.w + hr.w)));
        z = 1.f / (1.f + expf(-(iz.w + hz.w)));
        o.w = (1.f - z) * tanhf(in.w + r * hn.w) + z * hv.w;
    }
    *(float4*)(g_newh + (size_t)c * HID + j4) = o;
}

__global__ void colsum_part()
{
    int jb = blockIdx.x, l = blockIdx.y, cs = blockIdx.z, t = threadIdx.x;
    int j = jb * 128 + t;
    const float* p = g_newh + ((size_t)(l * CPL + cs * 128)) * HID + j;
    float s = 0.f;
    for (int c = 0; c < 128; c++) s += p[(size_t)c * HID];
    g_cs[(l * 8 + cs) * HID + j] = s;
}
__global__ void colsum_red()
{
    int jb = blockIdx.x, l = blockIdx.y, t = threadIdx.x;
    int j = jb * 128 + t;
    float s = 0.f;
    for (int cs = 0; cs < 8; cs++) s += g_cs[(l * 8 + cs) * HID + j];
    g_lm[l * HID + j] = s * (1.f / CPL);
}

template<int SRC>
__global__ void pred_part(const float* __restrict__ W)
{
    int ks = blockIdx.x, l = blockIdx.y, t = threadIdx.x;
    const float* v = (SRC == 0 ? g_lm + (l + 1) * HID : g_pz + l * HID) + ks * 64;
    const float* Wp = W + (size_t)l * HID * HID + (size_t)ks * 64 * HID;
    float acc[4] = {0.f, 0.f, 0.f, 0.f};
    for (int i = 0; i < 64; i++) {
        float a = v[i];
#pragma unroll
        for (int q = 0; q < 4; q++) acc[q] = fmaf(a, Wp[(size_t)i * HID + t + 256 * q], acc[q]);
    }
    float* dst = (SRC == 0 ? g_pp : g_pp2) + (l * 16 + ks) * HID;
#pragma unroll
    for (int q = 0; q < 4; q++) dst[t + 256 * q] = acc[q];
}
template<int SRC>
__global__ void pred_red(const float* __restrict__ b)
{
    int l = blockIdx.x, t = threadIdx.x;
    const float* part = (SRC == 0 ? g_pp : g_pp2) + l * 16 * HID;
#pragma unroll
    for (int q = 0; q < 4; q++) {
        int n = t + 256 * q;
        float s = b[l * HID + n];
        for (int ks = 0; ks < 16; ks++) s += part[ks * HID + n];
        if (SRC == 0) g_pz[l * HID + n] = fmaxf(s, 0.f);
        else          g_pred[l * HID + n] = s;
    }
}

__global__ void finalize_kernel()
{
    int j = threadIdx.x;
    float lm0 = g_lm[j], lm1 = g_lm[HID + j], lm2 = g_lm[2 * HID + j], lm3 = g_lm[3 * HID + j];
    float pe0 = (g_pred[j] - lm0) * 0.05f;
    float pe1 = (g_pred[HID + j] - lm1) * 0.05f;
    float pe2 = (g_pred[2 * HID + j] - lm2) * 0.05f;
    float d0 = pe0, d1 = pe1 - 0.5f * pe0, d2 = pe2 - 0.5f * pe1, d3 = -0.5f * pe2;
    g_delta[j] = d0; g_delta[HID + j] = d1; g_delta[2 * HID + j] = d2; g_delta[3 * HID + j] = d3;
    float m0 = lm0 + d0, m1 = lm1 + d1, m2 = lm2 + d2, m3 = lm3 + d3;
    g_mdelta[j] = m0; g_mdelta[HID + j] = m1; g_mdelta[2 * HID + j] = m2; g_mdelta[3 * HID + j] = m3;
    g_gop[j] = (m0 + m1 + m2 + m3) * 0.25f;
}

__global__ void hh_kernel(float* __restrict__ out, const int* __restrict__ stepp)
{
    int idx = blockIdx.x * blockDim.x + threadIdx.x;
    int c = idx >> 10, j = idx & 1023;
    int l = c >> 10, cl = c & 1023;
    float d = g_delta[l * HID + j];
    float v = 0.7225f * (g_newh[idx] + d) + 0.2775f * g_mdelta[l * HID + j];
    if (*stepp > 5 && cl < (CPL / 4)) v = 0.85f * v + 0.15f * g_gop[j];
    out[513 + idx] = v;
}

__global__ void combined_part(const float* __restrict__ W)
{
    int ks = blockIdx.x, nb = blockIdx.y, t = threadIdx.x;
    int n = nb * 256 + t;
    const float* Wp = W + (size_t)ks * 256 * OUTD;
    const float* lm = g_lm + ks * 256;
    float s = 0.f;
    for (int i = 0; i < 256; i++) s = fmaf(lm[i], Wp[(size_t)i * OUTD + n], s);
    g_cp[ks * OUTD + n] = s;
}
__global__ void combined_red(const float* __restrict__ b, float* __restrict__ out)
{
    int n = blockIdx.x * 256 + threadIdx.x;
    float s = b[n];
    for (int ks = 0; ks < 16; ks++) s += g_cp[ks * OUTD + n];
    out[n] = s;
}

__global__ void avgten_kernel(float* __restrict__ out)
{
    __shared__ float sm[1024];
    int t = threadIdx.x;
    float s = 0.f;
#pragma unroll
    for (int q = 0; q < 4; q++) s += g_out[(size_t)(t + 1024 * q) * MEMK + OUTD];
    sm[t] = s; __syncthreads();
    for (int o = 512; o > 0; o >>= 1) { if (t < o) sm[t] += sm[t + o]; __syncthreads(); }
    if (t == 0) out[OUTD] = sm[0] * (1.f / NC);
}

// ================= host =================
template<class T> static T* sym(const T& s)
{
    void* p = nullptr;
    cudaGetSymbolAddress(&p, s);
    return (T*)p;
}

extern "C" void kernel_launch(void* const* d_in, const int* in_sizes, int n_in,
                              void* d_out, int out_size)
{
    const float* x     = (const float*)d_in[0];
    const float* hid   = (const float*)d_in[1];
    const float* eaW1  = (const float*)d_in[2];
    const float* eab1  = (const float*)d_in[3];
    const float* eaW2  = (const float*)d_in[4];
    const float* eab2  = (const float*)d_in[5];
    const float* egW1  = (const float*)d_in[6];
    const float* egb1  = (const float*)d_in[7];
    const float* egW2  = (const float*)d_in[8];
    const float* egb2  = (const float*)d_in[9];
    const float* Wih   = (const float*)d_in[10];
    const float* Whh   = (const float*)d_in[11];
    const float* bih   = (const float*)d_in[12];
    const float* bhh   = (const float*)d_in[13];
    const float* pW1   = (const float*)d_in[14];
    const float* pb1   = (const float*)d_in[15];
    const float* pW2   = (const float*)d_in[16];
    const float* pb2   = (const float*)d_in[17];
    const float* peiW  = (const float*)d_in[18];
    const float* peib  = (const float*)d_in[19];
    const int*   stepp = (const int*)d_in[20];
    float* out = (float*)d_out;

    const int SM128 = 3 * (128 + BN) * PROW * 2;   // 110592
    const int SM64  = 3 * (64 + BN) * PROW * 2;    // 82944
    cudaFuncSetAttribute(tgemm<128>, cudaFuncAttributeMaxDynamicSharedMemorySize, SM128);
    cudaFuncSetAttribute(tgemm<64>,  cudaFuncAttributeMaxDynamicSharedMemorySize, SM64);

    float* zab  = sym(g_zab[0]);
    float* outb = sym(g_out[0]);
    float* gi   = sym(g_gi[0]);
    float* gh   = sym(g_gh[0]);
    float* xa2  = sym(g_xa2[0]);
    float* b2d  = sym(g_b2d[0]);
    __nv_bfloat16* A2h  = sym(g_A2h[0]);
    __nv_bfloat16* A2m  = sym(g_A2m[0]);
    __nv_bfloat16* zab2 = sym(g_zab2[0]);
    __nv_bfloat16* W2hh = sym(g_W2hh[0]);
    __nv_bfloat16* W2ih = sym(g_W2ih[0]);
    __nv_bfloat16* W1b2 = sym(g_W1b2[0]);
    __nv_bfloat16* W2b2 = sym(g_W2b2[0]);

    auto nb = [](long total) { return (unsigned)((total + 255) / 256); };

    // ---- launches 0-2: gh prerequisites ----
    split2v_k<<<nb((long)NC * 1024 / 8), 256>>>(hid, A2h, 1024, (long)NC * 1024 / 8);   // 0
    split2v_k<<<nb((long)NLV * G3 * 1024 / 8), 256>>>(Whh, W2hh, 1024,
                                                      (long)NLV * G3 * 1024 / 8);       // 1
    convW1_k<<<nb(4L * 256 * 1024), 256>>>(eaW1, egW1);                                 // 2

    // ---- launch 3 (profiled): gh GEMM ----
    tgemm<128><<<dim3(G3 / BN, CPL / 128, NLV), 256, SM128>>>(                          // 3
        A2h, (long)CPL * 2048, W2hh, (long)G3 * 2048,
        gh, G3, (long)CPL * G3, 1024, bhh, G3, 0);

    // ---- remaining conversions ----
    xa_part<<<dim3(4, NLV, 2), 128>>>(x, eaW1, egW1);
    xa_red<<<dim3(NLV, 2), 128>>>(eab1, egb1);
    convW2_k<<<nb(4L * 512 * 256), 256>>>(eaW2, egW2);
    b2diff_k<<<8, 256>>>(eab2, egb2);
    split2pv_k<<<nb(12288L * 72), 256>>>(Wih, MEMK, W2ih, MEMK, KP_M, 12288L * 72);

    // ---- MLP1: [za|zg] = relu(h @ [W1a;W1g]^T + xa2) ----
    tgemm<64><<<dim3(256 / BN, CPL / 64, NLV), 256, SM64>>>(
        A2h, (long)CPL * 2048, W1b2, 256L * 2048,
        zab, 256, (long)CPL * 256, 1024, xa2, 256, 1);

    // ---- MLP2: out = [za|zg] @ [W2a;-W2g]^T + (b2a-b2g) ----
    split2v_k<<<nb((long)NC * 256 / 8), 256>>>(zab, zab2, 256, (long)NC * 256 / 8);
    tgemm<64><<<dim3(OUTD / BN, CPL / 64, NLV), 256, SM64>>>(
        zab2, (long)CPL * 512, W2b2, (long)OUTD * 512,
        outb, MEMK, (long)CPL * MEMK, 256, b2d, OUTD, 0);

    // ---- tension + mem_in split ----
    tension_kernel<<<NC, 128>>>();
    split2pv_k<<<nb(4096L * 72), 256>>>(outb, MEMK, A2m, MEMK, KP_M, 4096L * 72);

    // ---- GRU gi ----
    tgemm<128><<<dim3(G3 / BN, CPL / 128, NLV), 256, SM128>>>(
        A2m, (long)CPL * 2 * KP_M, W2ih, (long)G3 * 2 * KP_M,
        gi, G3, (long)CPL * G3, KP_M, bih, G3, 0);

    // ---- gates + epilogue chain ----
    gate_kernel<<<(NC * HID / 4) / 256, 256>>>(hid);
    colsum_part<<<dim3(8, NLV, 8), 128>>>();
    colsum_red<<<dim3(8, NLV), 128>>>();
    pred_part<0><<<dim3(16, 3), 256>>>(pW1);
    pred_red<0><<<3, 256>>>(pb1);
    pred_part<1><<<dim3(16, 3), 256>>>(pW2);
    pred_red<1><<<3, 256>>>(pb2);
    finalize_kernel<<<1, 1024>>>();
    hh_kernel<<<(NC * HID) / 256, 256>>>(out, stepp);
    combined_part<<<dim3(16, 2), 256>>>(peiW);
    combined_red<<<2, 256>>>(peib, out);
    avgten_kernel<<<1, 1024>>>(out);
}

// round 14
// speedup vs baseline: 1.0982x; 1.0230x over previous
#include <cuda_runtime.h>
#include <cuda_bf16.h>
#include <cstdint>
#include <math.h>

#define NLV  4
#define CPL  1024
#define NC   4096
#define IND  512
#define HID  1024
#define OUTD 512
#define MLPD 128
#define G3   3072
#define MEMK 513

#define KP_M   576   // 513 padded

// ---------------- scratch ----------------
__device__ float g_xa2[NLV * 256];
__device__ float g_xap[2 * NLV * 4 * 128];
__device__ float g_zab[NC * 256];
__device__ float g_out[NC * MEMK];
__device__ float g_gi[(size_t)NC * G3];
__device__ float g_gh[(size_t)NC * G3];
__device__ float g_newh[NC * HID];
__device__ float g_lm[NLV * HID];
__device__ float g_cs[NLV * 8 * HID];
__device__ float g_pz[3 * HID];
__device__ float g_pp[3 * 16 * HID];
__device__ float g_pp2[3 * 16 * HID];
__device__ float g_pred[3 * HID];
__device__ float g_delta[NLV * HID];
__device__ float g_mdelta[NLV * HID];
__device__ float g_gop[HID];
__device__ float g_b2d[NLV * OUTD];
__device__ float g_cp[16 * OUTD];

// [hi|lo] bf16 buffers (row length = 2K)
__device__ __align__(16) __nv_bfloat16 g_A2h[(size_t)NC * 2048];
__device__ __align__(16) __nv_bfloat16 g_A2m[(size_t)NC * 2 * KP_M];
__device__ __align__(16) __nv_bfloat16 g_zab2[(size_t)NC * 512];
__device__ __align__(16) __nv_bfloat16 g_W2hh[(size_t)NLV * G3 * 2048];
__device__ __align__(16) __nv_bfloat16 g_W2ih[(size_t)NLV * G3 * 2 * KP_M];
__device__ __align__(16) __nv_bfloat16 g_W1b2[(size_t)NLV * 256 * 2048];
__device__ __align__(16) __nv_bfloat16 g_W2b2[(size_t)NLV * OUTD * 512];

// ================= mma.sync GEMM (3-phase hi/lo, BK=64, 3-stage) =================
#define BN 128
#define BK 64
#define PROW 72

__device__ __forceinline__ void cp16(uint32_t dst, const void* src)
{
    asm volatile("cp.async.cg.shared.global [%0], [%1], 16;" :: "r"(dst), "l"(src));
}
__device__ __forceinline__ void cp_commit() { asm volatile("cp.async.commit_group;"); }
template<int N> __device__ __forceinline__ void cp_wait()
{
    asm volatile("cp.async.wait_group %0;" :: "n"(N));
}
__device__ __forceinline__ void ldsm4(uint32_t& r0, uint32_t& r1, uint32_t& r2, uint32_t& r3,
                                      uint32_t addr)
{
    asm volatile("ldmatrix.sync.aligned.m8n8.x4.shared.b16 {%0,%1,%2,%3}, [%4];"
                 : "=r"(r0), "=r"(r1), "=r"(r2), "=r"(r3) : "r"(addr));
}
__device__ __forceinline__ void mma16816(float* d, const uint32_t* a, const uint32_t* b)
{
    asm volatile("mma.sync.aligned.m16n8k16.row.col.f32.bf16.bf16.f32 "
                 "{%0,%1,%2,%3}, {%4,%5,%6,%7}, {%8,%9}, {%0,%1,%2,%3};"
                 : "+f"(d[0]), "+f"(d[1]), "+f"(d[2]), "+f"(d[3])
                 : "r"(a[0]), "r"(a[1]), "r"(a[2]), "r"(a[3]), "r"(b[0]), "r"(b[1]));
}

// A: [M, 2K] bf16 [hi|lo]; B: [N, 2K] bf16 [hi|lo].
// C = Ahi@Bhi^T + Ahi@Blo^T + Alo@Bhi^T (+bias, opt relu)
template<int BMT>
__global__ void __launch_bounds__(256, 2)
tgemm(const __nv_bfloat16* __restrict__ A, long sA,
      const __nv_bfloat16* __restrict__ B, long sB,
      float* __restrict__ C, int ldc, long sC,
      int K, const float* __restrict__ bias, int sBias, int act)
{
    constexpr int WM = BMT / 2;
    constexpr int NMI = WM / 16;
    constexpr int STGB = (BMT + BN) * PROW * 2;
    constexpr int BOFFB = BMT * PROW * 2;
    extern __shared__ __align__(16) char smem[];
    const int tid = threadIdx.x, wid = tid >> 5, lane = tid & 31;
    const int m0 = blockIdx.y * BMT, n0 = blockIdx.x * BN, lvl = blockIdx.z;
    const int lda = 2 * K;
    A += (long)lvl * sA + (long)m0 * lda;
    B += (long)lvl * sB + (long)n0 * lda;
    C += (long)lvl * sC;
    const float* bp = bias ? bias + (long)lvl * sBias + n0 : nullptr;

    const int wm = (wid >> 2) * WM, wn = (wid & 3) * 32;
    const uint32_t sb = (uint32_t)__cvta_generic_to_shared(smem);

    float acc[NMI][4][4] = {};
    const int ntp = K / BK, nt = 3 * ntp;
    const int rrow = tid >> 3, rch = tid & 7;

    auto load_tile = [&](int g, int s) {
        int p = (g >= 2 * ntp) ? 2 : (g >= ntp ? 1 : 0);
        int j = g - p * ntp;
        int ao = ((p == 2) ? K : 0) + j * BK;
        int bo = ((p == 1) ? K : 0) + j * BK;
        const __nv_bfloat16* Ag = A + ao;
        const __nv_bfloat16* Bg = B + bo;
        uint32_t base = sb + (uint32_t)s * STGB;
#pragma unroll
        for (int it = 0; it < BMT / 32; it++) {
            int r = rrow + it * 32;
            uint32_t o = (uint32_t)(r * PROW + rch * 8) * 2;
            cp16(base + o, Ag + (long)r * lda + rch * 8);
        }
#pragma unroll
        for (int it = 0; it < 4; it++) {
            int r = rrow + it * 32;
            uint32_t o = (uint32_t)(r * PROW + rch * 8) * 2;
            cp16(base + BOFFB + o, Bg + (long)r * lda + rch * 8);
        }
    };

    load_tile(0, 0); cp_commit();
    load_tile(1, 1); cp_commit();

    // precomputed per-warp ldsm addresses (k-independent parts)
    const int b_n  = wn + (lane & 7) + ((lane & 16) ? 8 : 0);   // +16 for nb2=1
    const int b_kk = (lane & 8) ? 8 : 0;
    const int a_r  = wm + (lane & 7) + ((lane & 8) ? 8 : 0);    // +16*mi
    const int a_kk = (lane & 16) ? 8 : 0;

    int st = 0;
    for (int kt = 0; kt < nt; kt++) {
        cp_wait<1>();
        __syncthreads();
        if (kt + 2 < nt) {
            int s2 = st + 2; if (s2 >= 3) s2 -= 3;
            load_tile(kt + 2, s2); cp_commit();
        }
        uint32_t as = sb + (uint32_t)st * STGB;
        uint32_t bs = as + BOFFB;
#pragma unroll
        for (int ks = 0; ks < 4; ks++) {
            int k0 = ks * 16;
            // ---- batch ALL ldsm first (latencies overlap), then all mma ----
            uint32_t b[4][2];
#pragma unroll
            for (int nb2 = 0; nb2 < 2; nb2++) {
                uint32_t r0, r1, r2, r3;
                ldsm4(r0, r1, r2, r3,
                      bs + (uint32_t)((b_n + nb2 * 16) * PROW + k0 + b_kk) * 2);
                b[nb2 * 2][0] = r0; b[nb2 * 2][1] = r1;
                b[nb2 * 2 + 1][0] = r2; b[nb2 * 2 + 1][1] = r3;
            }
            uint32_t afr[NMI][4];
#pragma unroll
            for (int mi = 0; mi < NMI; mi++)
                ldsm4(afr[mi][0], afr[mi][1], afr[mi][2], afr[mi][3],
                      as + (uint32_t)((a_r + mi * 16) * PROW + k0 + a_kk) * 2);
#pragma unroll
            for (int mi = 0; mi < NMI; mi++)
#pragma unroll
                for (int ni = 0; ni < 4; ni++)
                    mma16816(acc[mi][ni], afr[mi], b[ni]);
        }
        if (++st == 3) st = 0;
    }

    const int tr = lane >> 2, tc = (lane & 3) * 2;
#pragma unroll
    for (int mi = 0; mi < NMI; mi++) {
        int r = m0 + wm + mi * 16 + tr;
#pragma unroll
        for (int ni = 0; ni < 4; ni++) {
            int c  = wn + ni * 8 + tc;
            float b0 = bp ? bp[c] : 0.f, b1 = bp ? bp[c + 1] : 0.f;
            float v0 = acc[mi][ni][0] + b0, v1 = acc[mi][ni][1] + b1;
            float v2 = acc[mi][ni][2] + b0, v3 = acc[mi][ni][3] + b1;
            if (act) { v0 = fmaxf(v0, 0.f); v1 = fmaxf(v1, 0.f);
                       v2 = fmaxf(v2, 0.f); v3 = fmaxf(v3, 0.f); }
            C[(long)r * ldc + n0 + c]           = v0;
            C[(long)r * ldc + n0 + c + 1]       = v1;
            C[(long)(r + 8) * ldc + n0 + c]     = v2;
            C[(long)(r + 8) * ldc + n0 + c + 1] = v3;
        }
    }
}

// ================= conversions ([hi|lo], 2K rows) =================
__global__ void split2v_k(const float* __restrict__ src, __nv_bfloat16* __restrict__ dst,
                          int K, long total8)
{
    long i = (long)blockIdx.x * 256 + threadIdx.x;
    if (i >= total8) return;
    int kc = K >> 3;
    long r = i / kc; int k = (int)(i - r * kc) * 8;
    const float* s = src + r * (long)K + k;
    float4 v0 = *(const float4*)s;
    float4 v1 = *(const float4*)(s + 4);
    float vv[8] = {v0.x, v0.y, v0.z, v0.w, v1.x, v1.y, v1.z, v1.w};
    union { __nv_bfloat162 h2[4]; uint4 u; } H, L;
#pragma unroll
    for (int j = 0; j < 4; j++) {
        float a = vv[2 * j], b = vv[2 * j + 1];
        __nv_bfloat16 ah = __float2bfloat16(a), bh = __float2bfloat16(b);
        __nv_bfloat16 al = __float2bfloat16(a - __bfloat162float(ah));
        __nv_bfloat16 bl = __float2bfloat16(b - __bfloat162float(bh));
        H.h2[j] = __nv_bfloat162(ah, bh);
        L.h2[j] = __nv_bfloat162(al, bl);
    }
    __nv_bfloat16* d = dst + r * (2L * K) + k;
    *(uint4*)d = H.u;
    *(uint4*)(d + K) = L.u;
}

// vectorized split for strided/padded rows (K=513 -> Kp=576)
__global__ void split2pv_k(const float* __restrict__ src, int lds,
                           __nv_bfloat16* __restrict__ dst, int K, int Kp, long total8)
{
    long i = (long)blockIdx.x * 256 + threadIdx.x;
    if (i >= total8) return;
    int ch = Kp >> 3;
    long r = i / ch; int kb = (int)(i - r * ch) * 8;
    const float* s = src + r * (long)lds + kb;
    union { __nv_bfloat162 h2[4]; uint4 u; } H, L;
#pragma unroll
    for (int j = 0; j < 4; j++) {
        int k0 = kb + 2 * j, k1 = kb + 2 * j + 1;
        float a = (k0 < K) ? s[2 * j] : 0.f;
        float b = (k1 < K) ? s[2 * j + 1] : 0.f;
        __nv_bfloat16 ah = __float2bfloat16(a), bh = __float2bfloat16(b);
        H.h2[j] = __nv_bfloat162(ah, bh);
        L.h2[j] = __nv_bfloat162(__float2bfloat16(a - __bfloat162float(ah)),
                                 __float2bfloat16(b - __bfloat162float(bh)));
    }
    __nv_bfloat16* d = dst + r * (2L * Kp) + kb;
    *(uint4*)d = H.u;
    *(uint4*)(d + Kp) = L.u;
}

__global__ void convW1_k(const float* __restrict__ ea, const float* __restrict__ eg)
{
    long i = (long)blockIdx.x * 256 + threadIdx.x;
    if (i >= 4L * 256 * 1024) return;
    int k = (int)(i & 1023); long t = i >> 10; int n = (int)(t & 255); int l = (int)(t >> 8);
    const float* src = ((n < 128) ? ea : eg) + (long)l * (IND + HID) * MLPD;
    float v = src[(long)(IND + k) * MLPD + (n & 127)];
    __nv_bfloat16 hi = __float2bfloat16(v);
    __nv_bfloat16 lo = __float2bfloat16(v - __bfloat162float(hi));
    __nv_bfloat16* d = g_W1b2 + ((long)l * 256 + n) * 2048;
    d[k] = hi; d[1024 + k] = lo;
}

__global__ void convW2_k(const float* __restrict__ W2a, const float* __restrict__ W2g)
{
    long i = (long)blockIdx.x * 256 + threadIdx.x;
    if (i >= 4L * 512 * 256) return;
    int k = (int)(i & 255); long t = i >> 8; int n = (int)(t & 511); int l = (int)(t >> 9);
    float v = (k < 128) ? W2a[(long)l * MLPD * OUTD + (long)k * OUTD + n]
                        : -W2g[(long)l * MLPD * OUTD + (long)(k - 128) * OUTD + n];
    __nv_bfloat16 hi = __float2bfloat16(v);
    __nv_bfloat16 lo = __float2bfloat16(v - __bfloat162float(hi));
    __nv_bfloat16* d = g_W2b2 + ((long)l * 512 + n) * 512;
    d[k] = hi; d[256 + k] = lo;
}

__global__ void b2diff_k(const float* __restrict__ a, const float* __restrict__ g)
{
    int i = blockIdx.x * 256 + threadIdx.x;
    g_b2d[i] = a[i] - g[i];
}

// ================= tail kernels =================
__global__ void xa_part(const float* __restrict__ x,
                        const float* __restrict__ eaW1, const float* __restrict__ egW1)
{
    int ks = blockIdx.x, l = blockIdx.y, which = blockIdx.z, t = threadIdx.x;
    const float* W = (which ? egW1 : eaW1) + (size_t)l * (IND + HID) * MLPD
                     + (size_t)ks * 128 * MLPD;
    const float* xs = x + ks * 128;
    float s = 0.f;
    for (int i = 0; i < 128; i++) s = fmaf(xs[i], W[(size_t)i * MLPD + t], s);
    g_xap[((which * NLV + l) * 4 + ks) * 128 + t] = s;
}
__global__ void xa_red(const float* __restrict__ eab1, const float* __restrict__ egb1)
{
    int l = blockIdx.x, which = blockIdx.y, t = threadIdx.x;
    const float* b = (which ? egb1 : eab1) + l * MLPD;
    float s = b[t];
    for (int ks = 0; ks < 4; ks++) s += g_xap[((which * NLV + l) * 4 + ks) * 128 + t];
    g_xa2[l * 256 + which * 128 + t] = s;
}

__global__ void tension_kernel()
{
    int c = blockIdx.x, t = threadIdx.x;
    const float* row = g_out + (size_t)c * MEMK;
    float s = 0.f;
#pragma unroll
    for (int q = 0; q < 4; q++) { float v = row[t + 128 * q]; s = fmaf(v, v, s); }
    __shared__ float sm[128];
    sm[t] = s; __syncthreads();
    for (int o = 64; o > 0; o >>= 1) { if (t < o) sm[t] += sm[t + o]; __syncthreads(); }
    if (t == 0) g_out[(size_t)c * MEMK + OUTD] = sm[0] * (1.f / OUTD);
}

__global__ void gate_kernel(const float* __restrict__ hid)
{
    int i4 = blockIdx.x * 256 + threadIdx.x;
    int c = i4 >> 8, j4 = (i4 & 255) * 4;
    size_t base = (size_t)c * G3 + j4;
    float4 ir = *(const float4*)(g_gi + base);
    float4 iz = *(const float4*)(g_gi + base + HID);
    float4 in = *(const float4*)(g_gi + base + 2 * HID);
    float4 hr = *(const float4*)(g_gh + base);
    float4 hz = *(const float4*)(g_gh + base + HID);
    float4 hn = *(const float4*)(g_gh + base + 2 * HID);
    float4 hv = *(const float4*)(hid + (size_t)c * HID + j4);
    float4 o;
    {
        float r = 1.f / (1.f + expf(-(ir.x + hr.x)));
        float z = 1.f / (1.f + expf(-(iz.x + hz.x)));
        o.x = (1.f - z) * tanhf(in.x + r * hn.x) + z * hv.x;
        r = 1.f / (1.f + expf(-(ir.y + hr.y)));
        z = 1.f / (1.f + expf(-(iz.y + hz.y)));
        o.y = (1.f - z) * tanhf(in.y + r * hn.y) + z * hv.y;
        r = 1.f / (1.f + expf(-(ir.z + hr.z)));
        z = 1.f / (1.f + expf(-(iz.z + hz.z)));
        o.z = (1.f - z) * tanhf(in.z + r * hn.z) + z * hv.z;
        r = 1.f / (1.f + expf(-(ir.w + hr.w)));
        z = 1.f / (1.f + expf(-(iz.w + hz.w)));
        o.w = (1.f - z) * tanhf(in.w + r * hn.w) + z * hv.w;
    }
    *(float4*)(g_newh + (size_t)c * HID + j4) = o;
}

__global__ void colsum_part()
{
    int jb = blockIdx.x, l = blockIdx.y, cs = blockIdx.z, t = threadIdx.x;
    int j = jb * 128 + t;
    const float* p = g_newh + ((size_t)(l * CPL + cs * 128)) * HID + j;
    float s = 0.f;
    for (int c = 0; c < 128; c++) s += p[(size_t)c * HID];
    g_cs[(l * 8 + cs) * HID + j] = s;
}
__global__ void colsum_red()
{
    int jb = blockIdx.x, l = blockIdx.y, t = threadIdx.x;
    int j = jb * 128 + t;
    float s = 0.f;
    for (int cs = 0; cs < 8; cs++) s += g_cs[(l * 8 + cs) * HID + j];
    g_lm[l * HID + j] = s * (1.f / CPL);
}

template<int SRC>
__global__ void pred_part(const float* __restrict__ W)
{
    int ks = blockIdx.x, l = blockIdx.y, t = threadIdx.x;
    const float* v = (SRC == 0 ? g_lm + (l + 1) * HID : g_pz + l * HID) + ks * 64;
    const float* Wp = W + (size_t)l * HID * HID + (size_t)ks * 64 * HID;
    float acc[4] = {0.f, 0.f, 0.f, 0.f};
    for (int i = 0; i < 64; i++) {
        float a = v[i];
#pragma unroll
        for (int q = 0; q < 4; q++) acc[q] = fmaf(a, Wp[(size_t)i * HID + t + 256 * q], acc[q]);
    }
    float* dst = (SRC == 0 ? g_pp : g_pp2) + (l * 16 + ks) * HID;
#pragma unroll
    for (int q = 0; q < 4; q++) dst[t + 256 * q] = acc[q];
}
template<int SRC>
__global__ void pred_red(const float* __restrict__ b)
{
    int l = blockIdx.x, t = threadIdx.x;
    const float* part = (SRC == 0 ? g_pp : g_pp2) + l * 16 * HID;
#pragma unroll
    for (int q = 0; q < 4; q++) {
        int n = t + 256 * q;
        float s = b[l * HID + n];
        for (int ks = 0; ks < 16; ks++) s += part[ks * HID + n];
        if (SRC == 0) g_pz[l * HID + n] = fmaxf(s, 0.f);
        else          g_pred[l * HID + n] = s;
    }
}

__global__ void finalize_kernel()
{
    int j = threadIdx.x;
    float lm0 = g_lm[j], lm1 = g_lm[HID + j], lm2 = g_lm[2 * HID + j], lm3 = g_lm[3 * HID + j];
    float pe0 = (g_pred[j] - lm0) * 0.05f;
    float pe1 = (g_pred[HID + j] - lm1) * 0.05f;
    float pe2 = (g_pred[2 * HID + j] - lm2) * 0.05f;
    float d0 = pe0, d1 = pe1 - 0.5f * pe0, d2 = pe2 - 0.5f * pe1, d3 = -0.5f * pe2;
    g_delta[j] = d0; g_delta[HID + j] = d1; g_delta[2 * HID + j] = d2; g_delta[3 * HID + j] = d3;
    float m0 = lm0 + d0, m1 = lm1 + d1, m2 = lm2 + d2, m3 = lm3 + d3;
    g_mdelta[j] = m0; g_mdelta[HID + j] = m1; g_mdelta[2 * HID + j] = m2; g_mdelta[3 * HID + j] = m3;
    g_gop[j] = (m0 + m1 + m2 + m3) * 0.25f;
}

__global__ void hh_kernel(float* __restrict__ out, const int* __restrict__ stepp)
{
    int idx = blockIdx.x * blockDim.x + threadIdx.x;
    int c = idx >> 10, j = idx & 1023;
    int l = c >> 10, cl = c & 1023;
    float d = g_delta[l * HID + j];
    float v = 0.7225f * (g_newh[idx] + d) + 0.2775f * g_mdelta[l * HID + j];
    if (*stepp > 5 && cl < (CPL / 4)) v = 0.85f * v + 0.15f * g_gop[j];
    out[513 + idx] = v;
}

__global__ void combined_part(const float* __restrict__ W)
{
    int ks = blockIdx.x, nb = blockIdx.y, t = threadIdx.x;
    int n = nb * 256 + t;
    const float* Wp = W + (size_t)ks * 256 * OUTD;
    const float* lm = g_lm + ks * 256;
    float s = 0.f;
    for (int i = 0; i < 256; i++) s = fmaf(lm[i], Wp[(size_t)i * OUTD + n], s);
    g_cp[ks * OUTD + n] = s;
}
__global__ void combined_red(const float* __restrict__ b, float* __restrict__ out)
{
    int n = blockIdx.x * 256 + threadIdx.x;
    float s = b[n];
    for (int ks = 0; ks < 16; ks++) s += g_cp[ks * OUTD + n];
    out[n] = s;
}

__global__ void avgten_kernel(float* __restrict__ out)
{
    __shared__ float sm[1024];
    int t = threadIdx.x;
    float s = 0.f;
#pragma unroll
    for (int q = 0; q < 4; q++) s += g_out[(size_t)(t + 1024 * q) * MEMK + OUTD];
    sm[t] = s; __syncthreads();
    for (int o = 512; o > 0; o >>= 1) { if (t < o) sm[t] += sm[t + o]; __syncthreads(); }
    if (t == 0) out[OUTD] = sm[0] * (1.f / NC);
}

// ================= host =================
template<class T> static T* sym(const T& s)
{
    void* p = nullptr;
    cudaGetSymbolAddress(&p, s);
    return (T*)p;
}

extern "C" void kernel_launch(void* const* d_in, const int* in_sizes, int n_in,
                              void* d_out, int out_size)
{
    const float* x     = (const float*)d_in[0];
    const float* hid   = (const float*)d_in[1];
    const float* eaW1  = (const float*)d_in[2];
    const float* eab1  = (const float*)d_in[3];
    const float* eaW2  = (const float*)d_in[4];
    const float* eab2  = (const float*)d_in[5];
    const float* egW1  = (const float*)d_in[6];
    const float* egb1  = (const float*)d_in[7];
    const float* egW2  = (const float*)d_in[8];
    const float* egb2  = (const float*)d_in[9];
    const float* Wih   = (const float*)d_in[10];
    const float* Whh   = (const float*)d_in[11];
    const float* bih   = (const float*)d_in[12];
    const float* bhh   = (const float*)d_in[13];
    const float* pW1   = (const float*)d_in[14];
    const float* pb1   = (const float*)d_in[15];
    const float* pW2   = (const float*)d_in[16];
    const float* pb2   = (const float*)d_in[17];
    const float* peiW  = (const float*)d_in[18];
    const float* peib  = (const float*)d_in[19];
    const int*   stepp = (const int*)d_in[20];
    float* out = (float*)d_out;

    const int SM128 = 3 * (128 + BN) * PROW * 2;   // 110592
    const int SM64  = 3 * (64 + BN) * PROW * 2;    // 82944
    cudaFuncSetAttribute(tgemm<128>, cudaFuncAttributeMaxDynamicSharedMemorySize, SM128);
    cudaFuncSetAttribute(tgemm<64>,  cudaFuncAttributeMaxDynamicSharedMemorySize, SM64);

    float* zab  = sym(g_zab[0]);
    float* outb = sym(g_out[0]);
    float* gi   = sym(g_gi[0]);
    float* gh   = sym(g_gh[0]);
    float* xa2  = sym(g_xa2[0]);
    float* b2d  = sym(g_b2d[0]);
    __nv_bfloat16* A2h  = sym(g_A2h[0]);
    __nv_bfloat16* A2m  = sym(g_A2m[0]);
    __nv_bfloat16* zab2 = sym(g_zab2[0]);
    __nv_bfloat16* W2hh = sym(g_W2hh[0]);
    __nv_bfloat16* W2ih = sym(g_W2ih[0]);
    __nv_bfloat16* W1b2 = sym(g_W1b2[0]);
    __nv_bfloat16* W2b2 = sym(g_W2b2[0]);

    auto nb = [](long total) { return (unsigned)((total + 255) / 256); };

    // ---- launches 0-2: gh prerequisites ----
    split2v_k<<<nb((long)NC * 1024 / 8), 256>>>(hid, A2h, 1024, (long)NC * 1024 / 8);   // 0
    split2v_k<<<nb((long)NLV * G3 * 1024 / 8), 256>>>(Whh, W2hh, 1024,
                                                      (long)NLV * G3 * 1024 / 8);       // 1
    convW1_k<<<nb(4L * 256 * 1024), 256>>>(eaW1, egW1);                                 // 2

    // ---- launch 3 (profiled): gh GEMM ----
    tgemm<128><<<dim3(G3 / BN, CPL / 128, NLV), 256, SM128>>>(                          // 3
        A2h, (long)CPL * 2048, W2hh, (long)G3 * 2048,
        gh, G3, (long)CPL * G3, 1024, bhh, G3, 0);

    // ---- remaining conversions ----
    xa_part<<<dim3(4, NLV, 2), 128>>>(x, eaW1, egW1);
    xa_red<<<dim3(NLV, 2), 128>>>(eab1, egb1);
    convW2_k<<<nb(4L * 512 * 256), 256>>>(eaW2, egW2);
    b2diff_k<<<8, 256>>>(eab2, egb2);
    split2pv_k<<<nb(12288L * 72), 256>>>(Wih, MEMK, W2ih, MEMK, KP_M, 12288L * 72);

    // ---- MLP1: [za|zg] = relu(h @ [W1a;W1g]^T + xa2) ----
    tgemm<64><<<dim3(256 / BN, CPL / 64, NLV), 256, SM64>>>(
        A2h, (long)CPL * 2048, W1b2, 256L * 2048,
        zab, 256, (long)CPL * 256, 1024, xa2, 256, 1);

    // ---- MLP2: out = [za|zg] @ [W2a;-W2g]^T + (b2a-b2g) ----
    split2v_k<<<nb((long)NC * 256 / 8), 256>>>(zab, zab2, 256, (long)NC * 256 / 8);
    tgemm<64><<<dim3(OUTD / BN, CPL / 64, NLV), 256, SM64>>>(
        zab2, (long)CPL * 512, W2b2, (long)OUTD * 512,
        outb, MEMK, (long)CPL * MEMK, 256, b2d, OUTD, 0);

    // ---- tension + mem_in split ----
    tension_kernel<<<NC, 128>>>();
    split2pv_k<<<nb(4096L * 72), 256>>>(outb, MEMK, A2m, MEMK, KP_M, 4096L * 72);

    // ---- GRU gi ----
    tgemm<128><<<dim3(G3 / BN, CPL / 128, NLV), 256, SM128>>>(
        A2m, (long)CPL * 2 * KP_M, W2ih, (long)G3 * 2 * KP_M,
        gi, G3, (long)CPL * G3, KP_M, bih, G3, 0);

    // ---- gates + epilogue chain ----
    gate_kernel<<<(NC * HID / 4) / 256, 256>>>(hid);
    colsum_part<<<dim3(8, NLV, 8), 128>>>();
    colsum_red<<<dim3(8, NLV), 128>>>();
    pred_part<0><<<dim3(16, 3), 256>>>(pW1);
    pred_red<0><<<3, 256>>>(pb1);
    pred_part<1><<<dim3(16, 3), 256>>>(pW2);
    pred_red<1><<<3, 256>>>(pb2);
    finalize_kernel<<<1, 1024>>>();
    hh_kernel<<<(NC * HID) / 256, 256>>>(out, stepp);
    combined_part<<<dim3(16, 2), 256>>>(peiW);
    combined_red<<<2, 256>>>(peib, out);
    avgten_kernel<<<1, 1024>>>(out);
}

// round 15
// speedup vs baseline: 1.1550x; 1.0517x over previous
#include <cuda_runtime.h>
#include <cuda_bf16.h>
#include <cstdint>
#include <math.h>

#define NLV  4
#define CPL  1024
#define NC   4096
#define IND  512
#define HID  1024
#define OUTD 512
#define MLPD 128
#define G3   3072
#define MEMK 513

#define KP_M   576   // 513 padded

// ---------------- scratch ----------------
__device__ float g_xa2[NLV * 256];
__device__ float g_xap[2 * NLV * 4 * 128];
__device__ float g_zab[NC * 256];
__device__ float g_out[NC * MEMK];
__device__ float g_gi[(size_t)NC * G3];
__device__ float g_gh[(size_t)NC * G3];
__device__ float g_newh[NC * HID];
__device__ float g_lm[NLV * HID];
__device__ float g_cs[NLV * 8 * HID];
__device__ float g_pz[3 * HID];
__device__ float g_pp[3 * 16 * HID];
__device__ float g_pp2[3 * 16 * HID];
__device__ float g_pred[3 * HID];
__device__ float g_delta[NLV * HID];
__device__ float g_mdelta[NLV * HID];
__device__ float g_gop[HID];
__device__ float g_b2d[NLV * OUTD];
__device__ float g_cp[16 * OUTD];

// [hi|lo] bf16 buffers (row length = 2K)
__device__ __align__(16) __nv_bfloat16 g_A2h[(size_t)NC * 2048];
__device__ __align__(16) __nv_bfloat16 g_A2m[(size_t)NC * 2 * KP_M];
__device__ __align__(16) __nv_bfloat16 g_zab2[(size_t)NC * 512];
__device__ __align__(16) __nv_bfloat16 g_W2hh[(size_t)NLV * G3 * 2048];
__device__ __align__(16) __nv_bfloat16 g_W2ih[(size_t)NLV * G3 * 2 * KP_M];
__device__ __align__(16) __nv_bfloat16 g_W1b2[(size_t)NLV * 256 * 2048];
__device__ __align__(16) __nv_bfloat16 g_W2b2[(size_t)NLV * OUTD * 512];

// ================= mma.sync GEMM (3-phase hi/lo, BK=64, 3-stage) =================
#define BN 128
#define BK 64
#define PROW 72

__device__ __forceinline__ void cp16(uint32_t dst, const void* src)
{
    asm volatile("cp.async.cg.shared.global [%0], [%1], 16;" :: "r"(dst), "l"(src));
}
__device__ __forceinline__ void cp_commit() { asm volatile("cp.async.commit_group;"); }
template<int N> __device__ __forceinline__ void cp_wait()
{
    asm volatile("cp.async.wait_group %0;" :: "n"(N));
}
__device__ __forceinline__ void ldsm4(uint32_t& r0, uint32_t& r1, uint32_t& r2, uint32_t& r3,
                                      uint32_t addr)
{
    asm volatile("ldmatrix.sync.aligned.m8n8.x4.shared.b16 {%0,%1,%2,%3}, [%4];"
                 : "=r"(r0), "=r"(r1), "=r"(r2), "=r"(r3) : "r"(addr));
}
__device__ __forceinline__ void mma16816(float* d, const uint32_t* a, const uint32_t* b)
{
    asm volatile("mma.sync.aligned.m16n8k16.row.col.f32.bf16.bf16.f32 "
                 "{%0,%1,%2,%3}, {%4,%5,%6,%7}, {%8,%9}, {%0,%1,%2,%3};"
                 : "+f"(d[0]), "+f"(d[1]), "+f"(d[2]), "+f"(d[3])
                 : "r"(a[0]), "r"(a[1]), "r"(a[2]), "r"(a[3]), "r"(b[0]), "r"(b[1]));
}

// A: [M, 2K] bf16 [hi|lo]; B: [N, 2K] bf16 [hi|lo].
// C = Ahi@Bhi^T + Ahi@Blo^T + Alo@Bhi^T (+bias, opt relu)
template<int BMT>
__global__ void __launch_bounds__(256, 2)
tgemm(const __nv_bfloat16* __restrict__ A, long sA,
      const __nv_bfloat16* __restrict__ B, long sB,
      float* __restrict__ C, int ldc, long sC,
      int K, const float* __restrict__ bias, int sBias, int act)
{
    constexpr int WM = BMT / 2;
    constexpr int NMI = WM / 16;
    constexpr int STGB = (BMT + BN) * PROW * 2;
    constexpr int BOFFB = BMT * PROW * 2;
    extern __shared__ __align__(16) char smem[];
    const int tid = threadIdx.x, wid = tid >> 5, lane = tid & 31;
    const int m0 = blockIdx.y * BMT, n0 = blockIdx.x * BN, lvl = blockIdx.z;
    const int lda = 2 * K;
    A += (long)lvl * sA + (long)m0 * lda;
    B += (long)lvl * sB + (long)n0 * lda;
    C += (long)lvl * sC;
    const float* bp = bias ? bias + (long)lvl * sBias + n0 : nullptr;

    const int wm = (wid >> 2) * WM, wn = (wid & 3) * 32;
    const uint32_t sb = (uint32_t)__cvta_generic_to_shared(smem);

    float acc[NMI][4][4] = {};
    const int ntp = K / BK, nt = 3 * ntp;
    const int rrow = tid >> 3, rch = tid & 7;

    auto load_tile = [&](int g, int s) {
        int p = (g >= 2 * ntp) ? 2 : (g >= ntp ? 1 : 0);
        int j = g - p * ntp;
        int ao = ((p == 2) ? K : 0) + j * BK;
        int bo = ((p == 1) ? K : 0) + j * BK;
        const __nv_bfloat16* Ag = A + ao;
        const __nv_bfloat16* Bg = B + bo;
        uint32_t base = sb + (uint32_t)s * STGB;
#pragma unroll
        for (int it = 0; it < BMT / 32; it++) {
            int r = rrow + it * 32;
            uint32_t o = (uint32_t)(r * PROW + rch * 8) * 2;
            cp16(base + o, Ag + (long)r * lda + rch * 8);
        }
#pragma unroll
        for (int it = 0; it < 4; it++) {
            int r = rrow + it * 32;
            uint32_t o = (uint32_t)(r * PROW + rch * 8) * 2;
            cp16(base + BOFFB + o, Bg + (long)r * lda + rch * 8);
        }
    };

    load_tile(0, 0); cp_commit();
    load_tile(1, 1); cp_commit();

    const int b_n  = wn + (lane & 7) + ((lane & 16) ? 8 : 0);
    const int b_kk = (lane & 8) ? 8 : 0;
    const int a_r  = wm + (lane & 7) + ((lane & 8) ? 8 : 0);
    const int a_kk = (lane & 16) ? 8 : 0;

    int st = 0;
    for (int kt = 0; kt < nt; kt++) {
        cp_wait<1>();
        __syncthreads();
        if (kt + 2 < nt) {
            int s2 = st + 2; if (s2 >= 3) s2 -= 3;
            load_tile(kt + 2, s2); cp_commit();
        }
        uint32_t as = sb + (uint32_t)st * STGB;
        uint32_t bs = as + BOFFB;
#pragma unroll
        for (int ks = 0; ks < 4; ks++) {
            int k0 = ks * 16;
            uint32_t b[4][2];
#pragma unroll
            for (int nb2 = 0; nb2 < 2; nb2++) {
                uint32_t r0, r1, r2, r3;
                ldsm4(r0, r1, r2, r3,
                      bs + (uint32_t)((b_n + nb2 * 16) * PROW + k0 + b_kk) * 2);
                b[nb2 * 2][0] = r0; b[nb2 * 2][1] = r1;
                b[nb2 * 2 + 1][0] = r2; b[nb2 * 2 + 1][1] = r3;
            }
            uint32_t afr[NMI][4];
#pragma unroll
            for (int mi = 0; mi < NMI; mi++)
                ldsm4(afr[mi][0], afr[mi][1], afr[mi][2], afr[mi][3],
                      as + (uint32_t)((a_r + mi * 16) * PROW + k0 + a_kk) * 2);
#pragma unroll
            for (int mi = 0; mi < NMI; mi++)
#pragma unroll
                for (int ni = 0; ni < 4; ni++)
                    mma16816(acc[mi][ni], afr[mi], b[ni]);
        }
        if (++st == 3) st = 0;
    }

    const int tr = lane >> 2, tc = (lane & 3) * 2;
#pragma unroll
    for (int mi = 0; mi < NMI; mi++) {
        int r = m0 + wm + mi * 16 + tr;
#pragma unroll
        for (int ni = 0; ni < 4; ni++) {
            int c  = wn + ni * 8 + tc;
            float b0 = bp ? bp[c] : 0.f, b1 = bp ? bp[c + 1] : 0.f;
            float v0 = acc[mi][ni][0] + b0, v1 = acc[mi][ni][1] + b1;
            float v2 = acc[mi][ni][2] + b0, v3 = acc[mi][ni][3] + b1;
            if (act) { v0 = fmaxf(v0, 0.f); v1 = fmaxf(v1, 0.f);
                       v2 = fmaxf(v2, 0.f); v3 = fmaxf(v3, 0.f); }
            C[(long)r * ldc + n0 + c]           = v0;
            C[(long)r * ldc + n0 + c + 1]       = v1;
            C[(long)(r + 8) * ldc + n0 + c]     = v2;
            C[(long)(r + 8) * ldc + n0 + c + 1] = v3;
        }
    }
}

// ================= conversions ([hi|lo], 2K rows) =================
__global__ void split2v_k(const float* __restrict__ src, __nv_bfloat16* __restrict__ dst,
                          int K, long total8)
{
    long i = (long)blockIdx.x * 256 + threadIdx.x;
    if (i >= total8) return;
    int kc = K >> 3;
    long r = i / kc; int k = (int)(i - r * kc) * 8;
    const float* s = src + r * (long)K + k;
    float4 v0 = *(const float4*)s;
    float4 v1 = *(const float4*)(s + 4);
    float vv[8] = {v0.x, v0.y, v0.z, v0.w, v1.x, v1.y, v1.z, v1.w};
    union { __nv_bfloat162 h2[4]; uint4 u; } H, L;
#pragma unroll
    for (int j = 0; j < 4; j++) {
        float a = vv[2 * j], b = vv[2 * j + 1];
        __nv_bfloat16 ah = __float2bfloat16(a), bh = __float2bfloat16(b);
        __nv_bfloat16 al = __float2bfloat16(a - __bfloat162float(ah));
        __nv_bfloat16 bl = __float2bfloat16(b - __bfloat162float(bh));
        H.h2[j] = __nv_bfloat162(ah, bh);
        L.h2[j] = __nv_bfloat162(al, bl);
    }
    __nv_bfloat16* d = dst + r * (2L * K) + k;
    *(uint4*)d = H.u;
    *(uint4*)(d + K) = L.u;
}

// vectorized split for strided/padded rows (K=513 -> Kp=576)
__global__ void split2pv_k(const float* __restrict__ src, int lds,
                           __nv_bfloat16* __restrict__ dst, int K, int Kp, long total8)
{
    long i = (long)blockIdx.x * 256 + threadIdx.x;
    if (i >= total8) return;
    int ch = Kp >> 3;
    long r = i / ch; int kb = (int)(i - r * ch) * 8;
    const float* s = src + r * (long)lds + kb;
    union { __nv_bfloat162 h2[4]; uint4 u; } H, L;
#pragma unroll
    for (int j = 0; j < 4; j++) {
        int k0 = kb + 2 * j, k1 = kb + 2 * j + 1;
        float a = (k0 < K) ? s[2 * j] : 0.f;
        float b = (k1 < K) ? s[2 * j + 1] : 0.f;
        __nv_bfloat16 ah = __float2bfloat16(a), bh = __float2bfloat16(b);
        H.h2[j] = __nv_bfloat162(ah, bh);
        L.h2[j] = __nv_bfloat162(__float2bfloat16(a - __bfloat162float(ah)),
                                 __float2bfloat16(b - __bfloat162float(bh)));
    }
    __nv_bfloat16* d = dst + r * (2L * Kp) + kb;
    *(uint4*)d = H.u;
    *(uint4*)(d + Kp) = L.u;
}

__global__ void convW1_k(const float* __restrict__ ea, const float* __restrict__ eg)
{
    long i = (long)blockIdx.x * 256 + threadIdx.x;
    if (i >= 4L * 256 * 1024) return;
    int k = (int)(i & 1023); long t = i >> 10; int n = (int)(t & 255); int l = (int)(t >> 8);
    const float* src = ((n < 128) ? ea : eg) + (long)l * (IND + HID) * MLPD;
    float v = src[(long)(IND + k) * MLPD + (n & 127)];
    __nv_bfloat16 hi = __float2bfloat16(v);
    __nv_bfloat16 lo = __float2bfloat16(v - __bfloat162float(hi));
    __nv_bfloat16* d = g_W1b2 + ((long)l * 256 + n) * 2048;
    d[k] = hi; d[1024 + k] = lo;
}

__global__ void convW2_k(const float* __restrict__ W2a, const float* __restrict__ W2g)
{
    long i = (long)blockIdx.x * 256 + threadIdx.x;
    if (i >= 4L * 512 * 256) return;
    int k = (int)(i & 255); long t = i >> 8; int n = (int)(t & 511); int l = (int)(t >> 9);
    float v = (k < 128) ? W2a[(long)l * MLPD * OUTD + (long)k * OUTD + n]
                        : -W2g[(long)l * MLPD * OUTD + (long)(k - 128) * OUTD + n];
    __nv_bfloat16 hi = __float2bfloat16(v);
    __nv_bfloat16 lo = __float2bfloat16(v - __bfloat162float(hi));
    __nv_bfloat16* d = g_W2b2 + ((long)l * 512 + n) * 512;
    d[k] = hi; d[256 + k] = lo;
}

__global__ void b2diff_k(const float* __restrict__ a, const float* __restrict__ g)
{
    int i = blockIdx.x * 256 + threadIdx.x;
    g_b2d[i] = a[i] - g[i];
}

// ================= tail kernels =================
__global__ void xa_part(const float* __restrict__ x,
                        const float* __restrict__ eaW1, const float* __restrict__ egW1)
{
    int ks = blockIdx.x, l = blockIdx.y, which = blockIdx.z, t = threadIdx.x;
    const float* W = (which ? egW1 : eaW1) + (size_t)l * (IND + HID) * MLPD
                     + (size_t)ks * 128 * MLPD;
    const float* xs = x + ks * 128;
    float s = 0.f;
    for (int i = 0; i < 128; i++) s = fmaf(xs[i], W[(size_t)i * MLPD + t], s);
    g_xap[((which * NLV + l) * 4 + ks) * 128 + t] = s;
}
__global__ void xa_red(const float* __restrict__ eab1, const float* __restrict__ egb1)
{
    int l = blockIdx.x, which = blockIdx.y, t = threadIdx.x;
    const float* b = (which ? egb1 : eab1) + l * MLPD;
    float s = b[t];
    for (int ks = 0; ks < 4; ks++) s += g_xap[((which * NLV + l) * 4 + ks) * 128 + t];
    g_xa2[l * 256 + which * 128 + t] = s;
}

__global__ void tension_kernel()
{
    int c = blockIdx.x, t = threadIdx.x;
    const float* row = g_out + (size_t)c * MEMK;
    float s = 0.f;
#pragma unroll
    for (int q = 0; q < 4; q++) { float v = row[t + 128 * q]; s = fmaf(v, v, s); }
    __shared__ float sm[128];
    sm[t] = s; __syncthreads();
    for (int o = 64; o > 0; o >>= 1) { if (t < o) sm[t] += sm[t + o]; __syncthreads(); }
    if (t == 0) g_out[(size_t)c * MEMK + OUTD] = sm[0] * (1.f / OUTD);
}

__global__ void gate_kernel(const float* __restrict__ hid)
{
    int i4 = blockIdx.x * 256 + threadIdx.x;
    int c = i4 >> 8, j4 = (i4 & 255) * 4;
    size_t base = (size_t)c * G3 + j4;
    float4 ir = *(const float4*)(g_gi + base);
    float4 iz = *(const float4*)(g_gi + base + HID);
    float4 in = *(const float4*)(g_gi + base + 2 * HID);
    float4 hr = *(const float4*)(g_gh + base);
    float4 hz = *(const float4*)(g_gh + base + HID);
    float4 hn = *(const float4*)(g_gh + base + 2 * HID);
    float4 hv = *(const float4*)(hid + (size_t)c * HID + j4);
    float4 o;
    {
        float r = 1.f / (1.f + expf(-(ir.x + hr.x)));
        float z = 1.f / (1.f + expf(-(iz.x + hz.x)));
        o.x = (1.f - z) * tanhf(in.x + r * hn.x) + z * hv.x;
        r = 1.f / (1.f + expf(-(ir.y + hr.y)));
        z = 1.f / (1.f + expf(-(iz.y + hz.y)));
        o.y = (1.f - z) * tanhf(in.y + r * hn.y) + z * hv.y;
        r = 1.f / (1.f + expf(-(ir.z + hr.z)));
        z = 1.f / (1.f + expf(-(iz.z + hz.z)));
        o.z = (1.f - z) * tanhf(in.z + r * hn.z) + z * hv.z;
        r = 1.f / (1.f + expf(-(ir.w + hr.w)));
        z = 1.f / (1.f + expf(-(iz.w + hz.w)));
        o.w = (1.f - z) * tanhf(in.w + r * hn.w) + z * hv.w;
    }
    *(float4*)(g_newh + (size_t)c * HID + j4) = o;
}

__global__ void colsum_part()
{
    int jb = blockIdx.x, l = blockIdx.y, cs = blockIdx.z, t = threadIdx.x;
    int j = jb * 128 + t;
    const float* p = g_newh + ((size_t)(l * CPL + cs * 128)) * HID + j;
    float s = 0.f;
    for (int c = 0; c < 128; c++) s += p[(size_t)c * HID];
    g_cs[(l * 8 + cs) * HID + j] = s;
}
__global__ void colsum_red()
{
    int jb = blockIdx.x, l = blockIdx.y, t = threadIdx.x;
    int j = jb * 128 + t;
    float s = 0.f;
    for (int cs = 0; cs < 8; cs++) s += g_cs[(l * 8 + cs) * HID + j];
    g_lm[l * HID + j] = s * (1.f / CPL);
}

template<int SRC>
__global__ void pred_part(const float* __restrict__ W)
{
    int ks = blockIdx.x, l = blockIdx.y, t = threadIdx.x;
    const float* v = (SRC == 0 ? g_lm + (l + 1) * HID : g_pz + l * HID) + ks * 64;
    const float* Wp = W + (size_t)l * HID * HID + (size_t)ks * 64 * HID;
    float acc[4] = {0.f, 0.f, 0.f, 0.f};
    for (int i = 0; i < 64; i++) {
        float a = v[i];
#pragma unroll
        for (int q = 0; q < 4; q++) acc[q] = fmaf(a, Wp[(size_t)i * HID + t + 256 * q], acc[q]);
    }
    float* dst = (SRC == 0 ? g_pp : g_pp2) + (l * 16 + ks) * HID;
#pragma unroll
    for (int q = 0; q < 4; q++) dst[t + 256 * q] = acc[q];
}
template<int SRC>
__global__ void pred_red(const float* __restrict__ b)
{
    int l = blockIdx.x, t = threadIdx.x;
    const float* part = (SRC == 0 ? g_pp : g_pp2) + l * 16 * HID;
#pragma unroll
    for (int q = 0; q < 4; q++) {
        int n = t + 256 * q;
        float s = b[l * HID + n];
        for (int ks = 0; ks < 16; ks++) s += part[ks * HID + n];
        if (SRC == 0) g_pz[l * HID + n] = fmaxf(s, 0.f);
        else          g_pred[l * HID + n] = s;
    }
}

__global__ void finalize_kernel()
{
    int j = threadIdx.x;
    float lm0 = g_lm[j], lm1 = g_lm[HID + j], lm2 = g_lm[2 * HID + j], lm3 = g_lm[3 * HID + j];
    float pe0 = (g_pred[j] - lm0) * 0.05f;
    float pe1 = (g_pred[HID + j] - lm1) * 0.05f;
    float pe2 = (g_pred[2 * HID + j] - lm2) * 0.05f;
    float d0 = pe0, d1 = pe1 - 0.5f * pe0, d2 = pe2 - 0.5f * pe1, d3 = -0.5f * pe2;
    g_delta[j] = d0; g_delta[HID + j] = d1; g_delta[2 * HID + j] = d2; g_delta[3 * HID + j] = d3;
    float m0 = lm0 + d0, m1 = lm1 + d1, m2 = lm2 + d2, m3 = lm3 + d3;
    g_mdelta[j] = m0; g_mdelta[HID + j] = m1; g_mdelta[2 * HID + j] = m2; g_mdelta[3 * HID + j] = m3;
    g_gop[j] = (m0 + m1 + m2 + m3) * 0.25f;
}

__global__ void hh_kernel(float* __restrict__ out, const int* __restrict__ stepp)
{
    int idx = blockIdx.x * blockDim.x + threadIdx.x;
    int c = idx >> 10, j = idx & 1023;
    int l = c >> 10, cl = c & 1023;
    float d = g_delta[l * HID + j];
    float v = 0.7225f * (g_newh[idx] + d) + 0.2775f * g_mdelta[l * HID + j];
    if (*stepp > 5 && cl < (CPL / 4)) v = 0.85f * v + 0.15f * g_gop[j];
    out[513 + idx] = v;
}

__global__ void combined_part(const float* __restrict__ W)
{
    int ks = blockIdx.x, nb = blockIdx.y, t = threadIdx.x;
    int n = nb * 256 + t;
    const float* Wp = W + (size_t)ks * 256 * OUTD;
    const float* lm = g_lm + ks * 256;
    float s = 0.f;
    for (int i = 0; i < 256; i++) s = fmaf(lm[i], Wp[(size_t)i * OUTD + n], s);
    g_cp[ks * OUTD + n] = s;
}
__global__ void combined_red(const float* __restrict__ b, float* __restrict__ out)
{
    int n = blockIdx.x * 256 + threadIdx.x;
    float s = b[n];
    for (int ks = 0; ks < 16; ks++) s += g_cp[ks * OUTD + n];
    out[n] = s;
}

__global__ void avgten_kernel(float* __restrict__ out)
{
    __shared__ float sm[1024];
    int t = threadIdx.x;
    float s = 0.f;
#pragma unroll
    for (int q = 0; q < 4; q++) s += g_out[(size_t)(t + 1024 * q) * MEMK + OUTD];
    sm[t] = s; __syncthreads();
    for (int o = 512; o > 0; o >>= 1) { if (t < o) sm[t] += sm[t + o]; __syncthreads(); }
    if (t == 0) out[OUTD] = sm[0] * (1.f / NC);
}

// ================= host =================
template<class T> static T* sym(const T& s)
{
    void* p = nullptr;
    cudaGetSymbolAddress(&p, s);
    return (T*)p;
}

extern "C" void kernel_launch(void* const* d_in, const int* in_sizes, int n_in,
                              void* d_out, int out_size)
{
    const float* x     = (const float*)d_in[0];
    const float* hid   = (const float*)d_in[1];
    const float* eaW1  = (const float*)d_in[2];
    const float* eab1  = (const float*)d_in[3];
    const float* eaW2  = (const float*)d_in[4];
    const float* eab2  = (const float*)d_in[5];
    const float* egW1  = (const float*)d_in[6];
    const float* egb1  = (const float*)d_in[7];
    const float* egW2  = (const float*)d_in[8];
    const float* egb2  = (const float*)d_in[9];
    const float* Wih   = (const float*)d_in[10];
    const float* Whh   = (const float*)d_in[11];
    const float* bih   = (const float*)d_in[12];
    const float* bhh   = (const float*)d_in[13];
    const float* pW1   = (const float*)d_in[14];
    const float* pb1   = (const float*)d_in[15];
    const float* pW2   = (const float*)d_in[16];
    const float* pb2   = (const float*)d_in[17];
    const float* peiW  = (const float*)d_in[18];
    const float* peib  = (const float*)d_in[19];
    const int*   stepp = (const int*)d_in[20];
    float* out = (float*)d_out;

    const int SM128 = 3 * (128 + BN) * PROW * 2;   // 110592
    const int SM64  = 3 * (64 + BN) * PROW * 2;    // 82944
    cudaFuncSetAttribute(tgemm<128>, cudaFuncAttributeMaxDynamicSharedMemorySize, SM128);
    cudaFuncSetAttribute(tgemm<64>,  cudaFuncAttributeMaxDynamicSharedMemorySize, SM64);

    // persistent side stream + events (created once; launched work is identical
    // on every call — no device memory involved)
    static cudaStream_t s1 = nullptr;
    static cudaEvent_t evF = nullptr, evJ = nullptr;
    if (!s1) {
        cudaStreamCreateWithFlags(&s1, cudaStreamNonBlocking);
        cudaEventCreateWithFlags(&evF, cudaEventDisableTiming);
        cudaEventCreateWithFlags(&evJ, cudaEventDisableTiming);
    }

    float* zab  = sym(g_zab[0]);
    float* outb = sym(g_out[0]);
    float* gi   = sym(g_gi[0]);
    float* gh   = sym(g_gh[0]);
    float* xa2  = sym(g_xa2[0]);
    float* b2d  = sym(g_b2d[0]);
    __nv_bfloat16* A2h  = sym(g_A2h[0]);
    __nv_bfloat16* A2m  = sym(g_A2m[0]);
    __nv_bfloat16* zab2 = sym(g_zab2[0]);
    __nv_bfloat16* W2hh = sym(g_W2hh[0]);
    __nv_bfloat16* W2ih = sym(g_W2ih[0]);
    __nv_bfloat16* W1b2 = sym(g_W1b2[0]);
    __nv_bfloat16* W2b2 = sym(g_W2b2[0]);

    auto nb = [](long total) { return (unsigned)((total + 255) / 256); };

    // ---- fork side stream (runs conversions concurrently with gh GEMM) ----
    cudaEventRecord(evF, 0);
    cudaStreamWaitEvent(s1, evF, 0);

    // side stream: everything gh does NOT need
    convW1_k<<<nb(4L * 256 * 1024), 256, 0, s1>>>(eaW1, egW1);
    xa_part<<<dim3(4, NLV, 2), 128, 0, s1>>>(x, eaW1, egW1);
    xa_red<<<dim3(NLV, 2), 128, 0, s1>>>(eab1, egb1);
    convW2_k<<<nb(4L * 512 * 256), 256, 0, s1>>>(eaW2, egW2);
    b2diff_k<<<8, 256, 0, s1>>>(eab2, egb2);
    split2pv_k<<<nb(12288L * 72), 256, 0, s1>>>(Wih, MEMK, W2ih, MEMK, KP_M, 12288L * 72);
    cudaEventRecord(evJ, s1);

    // main stream: gh path
    split2v_k<<<nb((long)NC * 1024 / 8), 256>>>(hid, A2h, 1024, (long)NC * 1024 / 8);
    split2v_k<<<nb((long)NLV * G3 * 1024 / 8), 256>>>(Whh, W2hh, 1024,
                                                      (long)NLV * G3 * 1024 / 8);
    tgemm<128><<<dim3(G3 / BN, CPL / 128, NLV), 256, SM128>>>(
        A2h, (long)CPL * 2048, W2hh, (long)G3 * 2048,
        gh, G3, (long)CPL * G3, 1024, bhh, G3, 0);

    // ---- join: MLP path needs side-stream outputs ----
    cudaStreamWaitEvent(0, evJ, 0);

    // MLP1: [za|zg] = relu(h @ [W1a;W1g]^T + xa2)
    tgemm<64><<<dim3(256 / BN, CPL / 64, NLV), 256, SM64>>>(
        A2h, (long)CPL * 2048, W1b2, 256L * 2048,
        zab, 256, (long)CPL * 256, 1024, xa2, 256, 1);

    // MLP2: out = [za|zg] @ [W2a;-W2g]^T + (b2a-b2g)
    split2v_k<<<nb((long)NC * 256 / 8), 256>>>(zab, zab2, 256, (long)NC * 256 / 8);
    tgemm<64><<<dim3(OUTD / BN, CPL / 64, NLV), 256, SM64>>>(
        zab2, (long)CPL * 512, W2b2, (long)OUTD * 512,
        outb, MEMK, (long)CPL * MEMK, 256, b2d, OUTD, 0);

    // tension + mem_in split
    tension_kernel<<<NC, 128>>>();
    split2pv_k<<<nb(4096L * 72), 256>>>(outb, MEMK, A2m, MEMK, KP_M, 4096L * 72);

    // GRU gi
    tgemm<128><<<dim3(G3 / BN, CPL / 128, NLV), 256, SM128>>>(
        A2m, (long)CPL * 2 * KP_M, W2ih, (long)G3 * 2 * KP_M,
        gi, G3, (long)CPL * G3, KP_M, bih, G3, 0);

    // gates + epilogue chain
    gate_kernel<<<(NC * HID / 4) / 256, 256>>>(hid);
    colsum_part<<<dim3(8, NLV, 8), 128>>>();
    colsum_red<<<dim3(8, NLV), 128>>>();
    pred_part<0><<<dim3(16, 3), 256>>>(pW1);
    pred_red<0><<<3, 256>>>(pb1);
    pred_part<1><<<dim3(16, 3), 256>>>(pW2);
    pred_red<1><<<3, 256>>>(pb2);
    finalize_kernel<<<1, 1024>>>();
    hh_kernel<<<(NC * HID) / 256, 256>>>(out, stepp);
    combined_part<<<dim3(16, 2), 256>>>(peiW);
    combined_red<<<2, 256>>>(peib, out);
    avgten_kernel<<<1, 1024>>>(out);
}

// round 16
// speedup vs baseline: 1.2178x; 1.0544x over previous
#include <cuda_runtime.h>
#include <cuda_bf16.h>
#include <cstdint>
#include <math.h>

#define NLV  4
#define CPL  1024
#define NC   4096
#define IND  512
#define HID  1024
#define OUTD 512
#define MLPD 128
#define G3   3072
#define MEMK 513

#define KP_M   576   // 513 padded

// ---------------- scratch ----------------
__device__ float g_xa2[NLV * 256];
__device__ float g_xap[2 * NLV * 4 * 128];
__device__ float g_zab[NC * 256];
__device__ float g_out[NC * MEMK];
__device__ float g_gi[(size_t)NC * G3];
__device__ float g_gh[(size_t)NC * G3];
__device__ float g_newh[NC * HID];
__device__ float g_lm[NLV * HID];
__device__ float g_cs[NLV * 8 * HID];
__device__ float g_pz[3 * HID];
__device__ float g_pp[3 * 16 * HID];
__device__ float g_pp2[3 * 16 * HID];
__device__ float g_pred[3 * HID];
__device__ float g_delta[NLV * HID];
__device__ float g_mdelta[NLV * HID];
__device__ float g_gop[HID];
__device__ float g_b2d[NLV * OUTD];
__device__ float g_cp[16 * OUTD];

// [hi|lo] bf16 buffers (row length = 2K)
__device__ __align__(16) __nv_bfloat16 g_A2h[(size_t)NC * 2048];
__device__ __align__(16) __nv_bfloat16 g_A2m[(size_t)NC * 2 * KP_M];
__device__ __align__(16) __nv_bfloat16 g_zab2[(size_t)NC * 512];
__device__ __align__(16) __nv_bfloat16 g_W2hh[(size_t)NLV * G3 * 2048];
__device__ __align__(16) __nv_bfloat16 g_W2ih[(size_t)NLV * G3 * 2 * KP_M];
__device__ __align__(16) __nv_bfloat16 g_W1b2[(size_t)NLV * 256 * 2048];
__device__ __align__(16) __nv_bfloat16 g_W2b2[(size_t)NLV * OUTD * 512];

// ================= mma.sync GEMM (3-phase hi/lo, BK=64, 3-stage) =================
#define BN 128
#define BK 64
#define PROW 72

__device__ __forceinline__ void cp16(uint32_t dst, const void* src)
{
    asm volatile("cp.async.cg.shared.global [%0], [%1], 16;" :: "r"(dst), "l"(src));
}
__device__ __forceinline__ void cp_commit() { asm volatile("cp.async.commit_group;"); }
template<int N> __device__ __forceinline__ void cp_wait()
{
    asm volatile("cp.async.wait_group %0;" :: "n"(N));
}
__device__ __forceinline__ void ldsm4(uint32_t& r0, uint32_t& r1, uint32_t& r2, uint32_t& r3,
                                      uint32_t addr)
{
    asm volatile("ldmatrix.sync.aligned.m8n8.x4.shared.b16 {%0,%1,%2,%3}, [%4];"
                 : "=r"(r0), "=r"(r1), "=r"(r2), "=r"(r3) : "r"(addr));
}
__device__ __forceinline__ void mma16816(float* d, const uint32_t* a, const uint32_t* b)
{
    asm volatile("mma.sync.aligned.m16n8k16.row.col.f32.bf16.bf16.f32 "
                 "{%0,%1,%2,%3}, {%4,%5,%6,%7}, {%8,%9}, {%0,%1,%2,%3};"
                 : "+f"(d[0]), "+f"(d[1]), "+f"(d[2]), "+f"(d[3])
                 : "r"(a[0]), "r"(a[1]), "r"(a[2]), "r"(a[3]), "r"(b[0]), "r"(b[1]));
}

// A: [M, 2K] bf16 [hi|lo]; B: [N, 2K] bf16 [hi|lo].
// C = Ahi@Bhi^T + Ahi@Blo^T + Alo@Bhi^T (+bias, opt relu)
template<int BMT>
__global__ void __launch_bounds__(256, 2)
tgemm(const __nv_bfloat16* __restrict__ A, long sA,
      const __nv_bfloat16* __restrict__ B, long sB,
      float* __restrict__ C, int ldc, long sC,
      int K, const float* __restrict__ bias, int sBias, int act)
{
    constexpr int WM = BMT / 2;
    constexpr int NMI = WM / 16;
    constexpr int STGB = (BMT + BN) * PROW * 2;
    constexpr int BOFFB = BMT * PROW * 2;
    extern __shared__ __align__(16) char smem[];
    const int tid = threadIdx.x, wid = tid >> 5, lane = tid & 31;
    const int m0 = blockIdx.y * BMT, n0 = blockIdx.x * BN, lvl = blockIdx.z;
    const int lda = 2 * K;
    A += (long)lvl * sA + (long)m0 * lda;
    B += (long)lvl * sB + (long)n0 * lda;
    C += (long)lvl * sC;
    const float* bp = bias ? bias + (long)lvl * sBias + n0 : nullptr;

    const int wm = (wid >> 2) * WM, wn = (wid & 3) * 32;
    const uint32_t sb = (uint32_t)__cvta_generic_to_shared(smem);

    float acc[NMI][4][4] = {};
    const int ntp = K / BK, nt = 3 * ntp;
    const int rrow = tid >> 3, rch = tid & 7;

    auto load_tile = [&](int g, int s) {
        int p = (g >= 2 * ntp) ? 2 : (g >= ntp ? 1 : 0);
        int j = g - p * ntp;
        int ao = ((p == 2) ? K : 0) + j * BK;
        int bo = ((p == 1) ? K : 0) + j * BK;
        const __nv_bfloat16* Ag = A + ao;
        const __nv_bfloat16* Bg = B + bo;
        uint32_t base = sb + (uint32_t)s * STGB;
#pragma unroll
        for (int it = 0; it < BMT / 32; it++) {
            int r = rrow + it * 32;
            uint32_t o = (uint32_t)(r * PROW + rch * 8) * 2;
            cp16(base + o, Ag + (long)r * lda + rch * 8);
        }
#pragma unroll
        for (int it = 0; it < 4; it++) {
            int r = rrow + it * 32;
            uint32_t o = (uint32_t)(r * PROW + rch * 8) * 2;
            cp16(base + BOFFB + o, Bg + (long)r * lda + rch * 8);
        }
    };

    load_tile(0, 0); cp_commit();
    load_tile(1, 1); cp_commit();

    const int b_n  = wn + (lane & 7) + ((lane & 16) ? 8 : 0);
    const int b_kk = (lane & 8) ? 8 : 0;
    const int a_r  = wm + (lane & 7) + ((lane & 8) ? 8 : 0);
    const int a_kk = (lane & 16) ? 8 : 0;

    int st = 0;
    for (int kt = 0; kt < nt; kt++) {
        cp_wait<1>();
        __syncthreads();
        if (kt + 2 < nt) {
            int s2 = st + 2; if (s2 >= 3) s2 -= 3;
            load_tile(kt + 2, s2); cp_commit();
        }
        uint32_t as = sb + (uint32_t)st * STGB;
        uint32_t bs = as + BOFFB;
#pragma unroll
        for (int ks = 0; ks < 4; ks++) {
            int k0 = ks * 16;
            uint32_t b[4][2];
#pragma unroll
            for (int nb2 = 0; nb2 < 2; nb2++) {
                uint32_t r0, r1, r2, r3;
                ldsm4(r0, r1, r2, r3,
                      bs + (uint32_t)((b_n + nb2 * 16) * PROW + k0 + b_kk) * 2);
                b[nb2 * 2][0] = r0; b[nb2 * 2][1] = r1;
                b[nb2 * 2 + 1][0] = r2; b[nb2 * 2 + 1][1] = r3;
            }
            uint32_t afr[NMI][4];
#pragma unroll
            for (int mi = 0; mi < NMI; mi++)
                ldsm4(afr[mi][0], afr[mi][1], afr[mi][2], afr[mi][3],
                      as + (uint32_t)((a_r + mi * 16) * PROW + k0 + a_kk) * 2);
#pragma unroll
            for (int mi = 0; mi < NMI; mi++)
#pragma unroll
                for (int ni = 0; ni < 4; ni++)
                    mma16816(acc[mi][ni], afr[mi], b[ni]);
        }
        if (++st == 3) st = 0;
    }

    const int tr = lane >> 2, tc = (lane & 3) * 2;
#pragma unroll
    for (int mi = 0; mi < NMI; mi++) {
        int r = m0 + wm + mi * 16 + tr;
#pragma unroll
        for (int ni = 0; ni < 4; ni++) {
            int c  = wn + ni * 8 + tc;
            float b0 = bp ? bp[c] : 0.f, b1 = bp ? bp[c + 1] : 0.f;
            float v0 = acc[mi][ni][0] + b0, v1 = acc[mi][ni][1] + b1;
            float v2 = acc[mi][ni][2] + b0, v3 = acc[mi][ni][3] + b1;
            if (act) { v0 = fmaxf(v0, 0.f); v1 = fmaxf(v1, 0.f);
                       v2 = fmaxf(v2, 0.f); v3 = fmaxf(v3, 0.f); }
            C[(long)r * ldc + n0 + c]           = v0;
            C[(long)r * ldc + n0 + c + 1]       = v1;
            C[(long)(r + 8) * ldc + n0 + c]     = v2;
            C[(long)(r + 8) * ldc + n0 + c + 1] = v3;
        }
    }
}

// ================= conversions ([hi|lo], 2K rows) =================
__global__ void split2v_k(const float* __restrict__ src, __nv_bfloat16* __restrict__ dst,
                          int K, long total8)
{
    long i = (long)blockIdx.x * 256 + threadIdx.x;
    if (i >= total8) return;
    int kc = K >> 3;
    long r = i / kc; int k = (int)(i - r * kc) * 8;
    const float* s = src + r * (long)K + k;
    float4 v0 = *(const float4*)s;
    float4 v1 = *(const float4*)(s + 4);
    float vv[8] = {v0.x, v0.y, v0.z, v0.w, v1.x, v1.y, v1.z, v1.w};
    union { __nv_bfloat162 h2[4]; uint4 u; } H, L;
#pragma unroll
    for (int j = 0; j < 4; j++) {
        float a = vv[2 * j], b = vv[2 * j + 1];
        __nv_bfloat16 ah = __float2bfloat16(a), bh = __float2bfloat16(b);
        __nv_bfloat16 al = __float2bfloat16(a - __bfloat162float(ah));
        __nv_bfloat16 bl = __float2bfloat16(b - __bfloat162float(bh));
        H.h2[j] = __nv_bfloat162(ah, bh);
        L.h2[j] = __nv_bfloat162(al, bl);
    }
    __nv_bfloat16* d = dst + r * (2L * K) + k;
    *(uint4*)d = H.u;
    *(uint4*)(d + K) = L.u;
}

// vectorized split for strided/padded rows (K=513 -> Kp=576)
__global__ void split2pv_k(const float* __restrict__ src, int lds,
                           __nv_bfloat16* __restrict__ dst, int K, int Kp, long total8)
{
    long i = (long)blockIdx.x * 256 + threadIdx.x;
    if (i >= total8) return;
    int ch = Kp >> 3;
    long r = i / ch; int kb = (int)(i - r * ch) * 8;
    const float* s = src + r * (long)lds + kb;
    union { __nv_bfloat162 h2[4]; uint4 u; } H, L;
#pragma unroll
    for (int j = 0; j < 4; j++) {
        int k0 = kb + 2 * j, k1 = kb + 2 * j + 1;
        float a = (k0 < K) ? s[2 * j] : 0.f;
        float b = (k1 < K) ? s[2 * j + 1] : 0.f;
        __nv_bfloat16 ah = __float2bfloat16(a), bh = __float2bfloat16(b);
        H.h2[j] = __nv_bfloat162(ah, bh);
        L.h2[j] = __nv_bfloat162(__float2bfloat16(a - __bfloat162float(ah)),
                                 __float2bfloat16(b - __bfloat162float(bh)));
    }
    __nv_bfloat16* d = dst + r * (2L * Kp) + kb;
    *(uint4*)d = H.u;
    *(uint4*)(d + Kp) = L.u;
}

__global__ void convW1_k(const float* __restrict__ ea, const float* __restrict__ eg)
{
    long i = (long)blockIdx.x * 256 + threadIdx.x;
    if (i >= 4L * 256 * 1024) return;
    int k = (int)(i & 1023); long t = i >> 10; int n = (int)(t & 255); int l = (int)(t >> 8);
    const float* src = ((n < 128) ? ea : eg) + (long)l * (IND + HID) * MLPD;
    float v = src[(long)(IND + k) * MLPD + (n & 127)];
    __nv_bfloat16 hi = __float2bfloat16(v);
    __nv_bfloat16 lo = __float2bfloat16(v - __bfloat162float(hi));
    __nv_bfloat16* d = g_W1b2 + ((long)l * 256 + n) * 2048;
    d[k] = hi; d[1024 + k] = lo;
}

__global__ void convW2_k(const float* __restrict__ W2a, const float* __restrict__ W2g)
{
    long i = (long)blockIdx.x * 256 + threadIdx.x;
    if (i >= 4L * 512 * 256) return;
    int k = (int)(i & 255); long t = i >> 8; int n = (int)(t & 511); int l = (int)(t >> 9);
    float v = (k < 128) ? W2a[(long)l * MLPD * OUTD + (long)k * OUTD + n]
                        : -W2g[(long)l * MLPD * OUTD + (long)(k - 128) * OUTD + n];
    __nv_bfloat16 hi = __float2bfloat16(v);
    __nv_bfloat16 lo = __float2bfloat16(v - __bfloat162float(hi));
    __nv_bfloat16* d = g_W2b2 + ((long)l * 512 + n) * 512;
    d[k] = hi; d[256 + k] = lo;
}

__global__ void b2diff_k(const float* __restrict__ a, const float* __restrict__ g)
{
    int i = blockIdx.x * 256 + threadIdx.x;
    g_b2d[i] = a[i] - g[i];
}

// ================= tail kernels =================
__global__ void xa_part(const float* __restrict__ x,
                        const float* __restrict__ eaW1, const float* __restrict__ egW1)
{
    int ks = blockIdx.x, l = blockIdx.y, which = blockIdx.z, t = threadIdx.x;
    const float* W = (which ? egW1 : eaW1) + (size_t)l * (IND + HID) * MLPD
                     + (size_t)ks * 128 * MLPD;
    const float* xs = x + ks * 128;
    float s = 0.f;
    for (int i = 0; i < 128; i++) s = fmaf(xs[i], W[(size_t)i * MLPD + t], s);
    g_xap[((which * NLV + l) * 4 + ks) * 128 + t] = s;
}
__global__ void xa_red(const float* __restrict__ eab1, const float* __restrict__ egb1)
{
    int l = blockIdx.x, which = blockIdx.y, t = threadIdx.x;
    const float* b = (which ? egb1 : eab1) + l * MLPD;
    float s = b[t];
    for (int ks = 0; ks < 4; ks++) s += g_xap[((which * NLV + l) * 4 + ks) * 128 + t];
    g_xa2[l * 256 + which * 128 + t] = s;
}

__global__ void tension_kernel()
{
    int c = blockIdx.x, t = threadIdx.x;
    const float* row = g_out + (size_t)c * MEMK;
    float s = 0.f;
#pragma unroll
    for (int q = 0; q < 4; q++) { float v = row[t + 128 * q]; s = fmaf(v, v, s); }
    __shared__ float sm[128];
    sm[t] = s; __syncthreads();
    for (int o = 64; o > 0; o >>= 1) { if (t < o) sm[t] += sm[t + o]; __syncthreads(); }
    if (t == 0) g_out[(size_t)c * MEMK + OUTD] = sm[0] * (1.f / OUTD);
}

__global__ void gate_kernel(const float* __restrict__ hid)
{
    int i4 = blockIdx.x * 256 + threadIdx.x;
    int c = i4 >> 8, j4 = (i4 & 255) * 4;
    size_t base = (size_t)c * G3 + j4;
    float4 ir = *(const float4*)(g_gi + base);
    float4 iz = *(const float4*)(g_gi + base + HID);
    float4 in = *(const float4*)(g_gi + base + 2 * HID);
    float4 hr = *(const float4*)(g_gh + base);
    float4 hz = *(const float4*)(g_gh + base + HID);
    float4 hn = *(const float4*)(g_gh + base + 2 * HID);
    float4 hv = *(const float4*)(hid + (size_t)c * HID + j4);
    float4 o;
    {
        float r = 1.f / (1.f + expf(-(ir.x + hr.x)));
        float z = 1.f / (1.f + expf(-(iz.x + hz.x)));
        o.x = (1.f - z) * tanhf(in.x + r * hn.x) + z * hv.x;
        r = 1.f / (1.f + expf(-(ir.y + hr.y)));
        z = 1.f / (1.f + expf(-(iz.y + hz.y)));
        o.y = (1.f - z) * tanhf(in.y + r * hn.y) + z * hv.y;
        r = 1.f / (1.f + expf(-(ir.z + hr.z)));
        z = 1.f / (1.f + expf(-(iz.z + hz.z)));
        o.z = (1.f - z) * tanhf(in.z + r * hn.z) + z * hv.z;
        r = 1.f / (1.f + expf(-(ir.w + hr.w)));
        z = 1.f / (1.f + expf(-(iz.w + hz.w)));
        o.w = (1.f - z) * tanhf(in.w + r * hn.w) + z * hv.w;
    }
    *(float4*)(g_newh + (size_t)c * HID + j4) = o;
}

__global__ void colsum_part()
{
    int jb = blockIdx.x, l = blockIdx.y, cs = blockIdx.z, t = threadIdx.x;
    int j = jb * 128 + t;
    const float* p = g_newh + ((size_t)(l * CPL + cs * 128)) * HID + j;
    float s = 0.f;
    for (int c = 0; c < 128; c++) s += p[(size_t)c * HID];
    g_cs[(l * 8 + cs) * HID + j] = s;
}
__global__ void colsum_red()
{
    int jb = blockIdx.x, l = blockIdx.y, t = threadIdx.x;
    int j = jb * 128 + t;
    float s = 0.f;
    for (int cs = 0; cs < 8; cs++) s += g_cs[(l * 8 + cs) * HID + j];
    g_lm[l * HID + j] = s * (1.f / CPL);
}

template<int SRC>
__global__ void pred_part(const float* __restrict__ W)
{
    int ks = blockIdx.x, l = blockIdx.y, t = threadIdx.x;
    const float* v = (SRC == 0 ? g_lm + (l + 1) * HID : g_pz + l * HID) + ks * 64;
    const float* Wp = W + (size_t)l * HID * HID + (size_t)ks * 64 * HID;
    float acc[4] = {0.f, 0.f, 0.f, 0.f};
    for (int i = 0; i < 64; i++) {
        float a = v[i];
#pragma unroll
        for (int q = 0; q < 4; q++) acc[q] = fmaf(a, Wp[(size_t)i * HID + t + 256 * q], acc[q]);
    }
    float* dst = (SRC == 0 ? g_pp : g_pp2) + (l * 16 + ks) * HID;
#pragma unroll
    for (int q = 0; q < 4; q++) dst[t + 256 * q] = acc[q];
}
template<int SRC>
__global__ void pred_red(const float* __restrict__ b)
{
    int l = blockIdx.x, t = threadIdx.x;
    const float* part = (SRC == 0 ? g_pp : g_pp2) + l * 16 * HID;
#pragma unroll
    for (int q = 0; q < 4; q++) {
        int n = t + 256 * q;
        float s = b[l * HID + n];
        for (int ks = 0; ks < 16; ks++) s += part[ks * HID + n];
        if (SRC == 0) g_pz[l * HID + n] = fmaxf(s, 0.f);
        else          g_pred[l * HID + n] = s;
    }
}

__global__ void finalize_kernel()
{
    int j = threadIdx.x;
    float lm0 = g_lm[j], lm1 = g_lm[HID + j], lm2 = g_lm[2 * HID + j], lm3 = g_lm[3 * HID + j];
    float pe0 = (g_pred[j] - lm0) * 0.05f;
    float pe1 = (g_pred[HID + j] - lm1) * 0.05f;
    float pe2 = (g_pred[2 * HID + j] - lm2) * 0.05f;
    float d0 = pe0, d1 = pe1 - 0.5f * pe0, d2 = pe2 - 0.5f * pe1, d3 = -0.5f * pe2;
    g_delta[j] = d0; g_delta[HID + j] = d1; g_delta[2 * HID + j] = d2; g_delta[3 * HID + j] = d3;
    float m0 = lm0 + d0, m1 = lm1 + d1, m2 = lm2 + d2, m3 = lm3 + d3;
    g_mdelta[j] = m0; g_mdelta[HID + j] = m1; g_mdelta[2 * HID + j] = m2; g_mdelta[3 * HID + j] = m3;
    g_gop[j] = (m0 + m1 + m2 + m3) * 0.25f;
}

__global__ void hh_kernel(float* __restrict__ out, const int* __restrict__ stepp)
{
    int idx = blockIdx.x * blockDim.x + threadIdx.x;
    int c = idx >> 10, j = idx & 1023;
    int l = c >> 10, cl = c & 1023;
    float d = g_delta[l * HID + j];
    float v = 0.7225f * (g_newh[idx] + d) + 0.2775f * g_mdelta[l * HID + j];
    if (*stepp > 5 && cl < (CPL / 4)) v = 0.85f * v + 0.15f * g_gop[j];
    out[513 + idx] = v;
}

__global__ void combined_part(const float* __restrict__ W)
{
    int ks = blockIdx.x, nb = blockIdx.y, t = threadIdx.x;
    int n = nb * 256 + t;
    const float* Wp = W + (size_t)ks * 256 * OUTD;
    const float* lm = g_lm + ks * 256;
    float s = 0.f;
    for (int i = 0; i < 256; i++) s = fmaf(lm[i], Wp[(size_t)i * OUTD + n], s);
    g_cp[ks * OUTD + n] = s;
}
__global__ void combined_red(const float* __restrict__ b, float* __restrict__ out)
{
    int n = blockIdx.x * 256 + threadIdx.x;
    float s = b[n];
    for (int ks = 0; ks < 16; ks++) s += g_cp[ks * OUTD + n];
    out[n] = s;
}

__global__ void avgten_kernel(float* __restrict__ out)
{
    __shared__ float sm[1024];
    int t = threadIdx.x;
    float s = 0.f;
#pragma unroll
    for (int q = 0; q < 4; q++) s += g_out[(size_t)(t + 1024 * q) * MEMK + OUTD];
    sm[t] = s; __syncthreads();
    for (int o = 512; o > 0; o >>= 1) { if (t < o) sm[t] += sm[t + o]; __syncthreads(); }
    if (t == 0) out[OUTD] = sm[0] * (1.f / NC);
}

// ================= host =================
template<class T> static T* sym(const T& s)
{
    void* p = nullptr;
    cudaGetSymbolAddress(&p, s);
    return (T*)p;
}

extern "C" void kernel_launch(void* const* d_in, const int* in_sizes, int n_in,
                              void* d_out, int out_size)
{
    const float* x     = (const float*)d_in[0];
    const float* hid   = (const float*)d_in[1];
    const float* eaW1  = (const float*)d_in[2];
    const float* eab1  = (const float*)d_in[3];
    const float* eaW2  = (const float*)d_in[4];
    const float* eab2  = (const float*)d_in[5];
    const float* egW1  = (const float*)d_in[6];
    const float* egb1  = (const float*)d_in[7];
    const float* egW2  = (const float*)d_in[8];
    const float* egb2  = (const float*)d_in[9];
    const float* Wih   = (const float*)d_in[10];
    const float* Whh   = (const float*)d_in[11];
    const float* bih   = (const float*)d_in[12];
    const float* bhh   = (const float*)d_in[13];
    const float* pW1   = (const float*)d_in[14];
    const float* pb1   = (const float*)d_in[15];
    const float* pW2   = (const float*)d_in[16];
    const float* pb2   = (const float*)d_in[17];
    const float* peiW  = (const float*)d_in[18];
    const float* peib  = (const float*)d_in[19];
    const int*   stepp = (const int*)d_in[20];
    float* out = (float*)d_out;

    const int SM128 = 3 * (128 + BN) * PROW * 2;   // 110592
    const int SM64  = 3 * (64 + BN) * PROW * 2;    // 82944
    cudaFuncSetAttribute(tgemm<128>, cudaFuncAttributeMaxDynamicSharedMemorySize, SM128);
    cudaFuncSetAttribute(tgemm<64>,  cudaFuncAttributeMaxDynamicSharedMemorySize, SM64);

    static cudaStream_t s1 = nullptr;
    static cudaEvent_t evA = nullptr, evJ = nullptr;
    if (!s1) {
        cudaStreamCreateWithFlags(&s1, cudaStreamNonBlocking);
        cudaEventCreateWithFlags(&evA, cudaEventDisableTiming);
        cudaEventCreateWithFlags(&evJ, cudaEventDisableTiming);
    }

    float* zab  = sym(g_zab[0]);
    float* outb = sym(g_out[0]);
    float* gi   = sym(g_gi[0]);
    float* gh   = sym(g_gh[0]);
    float* xa2  = sym(g_xa2[0]);
    float* b2d  = sym(g_b2d[0]);
    __nv_bfloat16* A2h  = sym(g_A2h[0]);
    __nv_bfloat16* A2m  = sym(g_A2m[0]);
    __nv_bfloat16* zab2 = sym(g_zab2[0]);
    __nv_bfloat16* W2hh = sym(g_W2hh[0]);
    __nv_bfloat16* W2ih = sym(g_W2ih[0]);
    __nv_bfloat16* W1b2 = sym(g_W1b2[0]);
    __nv_bfloat16* W2b2 = sym(g_W2b2[0]);

    auto nb = [](long total) { return (unsigned)((total + 255) / 256); };

    // ---- main: A2h split first (MLP1 on side stream needs it) ----
    split2v_k<<<nb((long)NC * 1024 / 8), 256>>>(hid, A2h, 1024, (long)NC * 1024 / 8);
    cudaEventRecord(evA, 0);
    cudaStreamWaitEvent(s1, evA, 0);

    // ---- side stream: entire MLP chain + conversions (independent of gh) ----
    convW1_k<<<nb(4L * 256 * 1024), 256, 0, s1>>>(eaW1, egW1);
    xa_part<<<dim3(4, NLV, 2), 128, 0, s1>>>(x, eaW1, egW1);
    xa_red<<<dim3(NLV, 2), 128, 0, s1>>>(eab1, egb1);
    tgemm<64><<<dim3(256 / BN, CPL / 64, NLV), 256, SM64, s1>>>(
        A2h, (long)CPL * 2048, W1b2, 256L * 2048,
        zab, 256, (long)CPL * 256, 1024, xa2, 256, 1);
    split2v_k<<<nb((long)NC * 256 / 8), 256, 0, s1>>>(zab, zab2, 256, (long)NC * 256 / 8);
    convW2_k<<<nb(4L * 512 * 256), 256, 0, s1>>>(eaW2, egW2);
    b2diff_k<<<8, 256, 0, s1>>>(eab2, egb2);
    tgemm<64><<<dim3(OUTD / BN, CPL / 64, NLV), 256, SM64, s1>>>(
        zab2, (long)CPL * 512, W2b2, (long)OUTD * 512,
        outb, MEMK, (long)CPL * MEMK, 256, b2d, OUTD, 0);
    tension_kernel<<<NC, 128, 0, s1>>>();
    split2pv_k<<<nb(4096L * 72), 256, 0, s1>>>(outb, MEMK, A2m, MEMK, KP_M, 4096L * 72);
    split2pv_k<<<nb(12288L * 72), 256, 0, s1>>>(Wih, MEMK, W2ih, MEMK, KP_M, 12288L * 72);
    cudaEventRecord(evJ, s1);

    // ---- main stream: gh path (concurrent with side chain) ----
    split2v_k<<<nb((long)NLV * G3 * 1024 / 8), 256>>>(Whh, W2hh, 1024,
                                                      (long)NLV * G3 * 1024 / 8);
    tgemm<128><<<dim3(G3 / BN, CPL / 128, NLV), 256, SM128>>>(
        A2h, (long)CPL * 2048, W2hh, (long)G3 * 2048,
        gh, G3, (long)CPL * G3, 1024, bhh, G3, 0);

    // ---- join: gi needs A2m + W2ih from side stream ----
    cudaStreamWaitEvent(0, evJ, 0);

    // GRU gi
    tgemm<128><<<dim3(G3 / BN, CPL / 128, NLV), 256, SM128>>>(
        A2m, (long)CPL * 2 * KP_M, W2ih, (long)G3 * 2 * KP_M,
        gi, G3, (long)CPL * G3, KP_M, bih, G3, 0);

    // gates + epilogue chain
    gate_kernel<<<(NC * HID / 4) / 256, 256>>>(hid);
    colsum_part<<<dim3(8, NLV, 8), 128>>>();
    colsum_red<<<dim3(8, NLV), 128>>>();
    pred_part<0><<<dim3(16, 3), 256>>>(pW1);
    pred_red<0><<<3, 256>>>(pb1);
    pred_part<1><<<dim3(16, 3), 256>>>(pW2);
    pred_red<1><<<3, 256>>>(pb2);
    finalize_kernel<<<1, 1024>>>();
    hh_kernel<<<(NC * HID) / 256, 256>>>(out, stepp);
    combined_part<<<dim3(16, 2), 256>>>(peiW);
    combined_red<<<2, 256>>>(peib, out);
    avgten_kernel<<<1, 1024>>>(out);
}